// round 7
// baseline (speedup 1.0000x reference)
#include <cuda_runtime.h>
#include <cuda_bf16.h>
#include <cstdint>

// ---------------------------------------------------------------------------
// DeepFM forward — HMMA bf16 3-term split GEMMs. R7:
//   R4 macro shape (256 thr, 8 warps, k-chunk 64, 2 CTAs/SM) +
//   A double-buffered (DRAM stream), B single-buffered (L2-hot weights) +
//   B-fragment register pipelining + fused epilogue column stats.
//   B=16384, F=26, D=32, DIN=832, H1=256, H2=128, V=100000
// ---------------------------------------------------------------------------

#define BATCH  16384
#define NF     26
#define ED     32
#define DIN    832
#define H1N    256
#define H2N    128
#define VOCAB  100000
#define BN_EPS 1e-5f

// ---- scratch ---------------------------------------------------------------
__device__ unsigned short g_Xh[(size_t)BATCH * DIN];
__device__ unsigned short g_Xl[(size_t)BATCH * DIN];
__device__ float          g_H1[(size_t)BATCH * H1N];
__device__ unsigned short g_A2h[(size_t)BATCH * H1N];
__device__ unsigned short g_A2l[(size_t)BATCH * H1N];
__device__ float          g_H2[(size_t)BATCH * H2N];
__device__ unsigned short g_W1Th[H1N * DIN], g_W1Tl[H1N * DIN];
__device__ unsigned short g_W2Th[H2N * H1N], g_W2Tl[H2N * H1N];
__device__ float g_fm[BATCH];
__device__ float g_stats1[2 * H1N];
__device__ float g_stats2[2 * H2N];
__device__ float g_sc1[H1N], g_sh1[H1N];

// ---- PTX helpers -----------------------------------------------------------
__device__ __forceinline__ uint32_t smem_u32(const void* p) {
    uint32_t a;
    asm("{ .reg .u64 t; cvta.to.shared.u64 t, %1; cvt.u32.u64 %0, t; }"
        : "=r"(a) : "l"(p));
    return a;
}
__device__ __forceinline__ void cp16cg(uint32_t dst, const void* src) {
    asm volatile("cp.async.cg.shared.global [%0], [%1], 16;"
                 :: "r"(dst), "l"(src));
}
__device__ __forceinline__ void cp16ca(uint32_t dst, const void* src) {
    asm volatile("cp.async.ca.shared.global [%0], [%1], 16;"
                 :: "r"(dst), "l"(src));
}
#define CP_COMMIT() asm volatile("cp.async.commit_group;" ::: "memory")

__device__ __forceinline__ void ldsm4(uint32_t* r, uint32_t addr) {
    asm volatile("ldmatrix.sync.aligned.m8n8.x4.shared.b16 {%0,%1,%2,%3}, [%4];"
                 : "=r"(r[0]), "=r"(r[1]), "=r"(r[2]), "=r"(r[3]) : "r"(addr));
}
__device__ __forceinline__ void mma16816(float* d, const uint32_t* a,
                                         const uint32_t* b) {
    asm volatile(
        "mma.sync.aligned.m16n8k16.row.col.f32.bf16.bf16.f32 "
        "{%0,%1,%2,%3}, {%4,%5,%6,%7}, {%8,%9}, {%0,%1,%2,%3};"
        : "+f"(d[0]), "+f"(d[1]), "+f"(d[2]), "+f"(d[3])
        : "r"(a[0]), "r"(a[1]), "r"(a[2]), "r"(a[3]), "r"(b[0]), "r"(b[1]));
}

// ---- tiny kernels ----------------------------------------------------------
__global__ void zero_stats_k() {
    int t = threadIdx.x;
    g_stats1[t] = 0.f; g_stats1[H1N + t] = 0.f;
    if (t < H2N) { g_stats2[t] = 0.f; g_stats2[H2N + t] = 0.f; }
}

__global__ void prep_w_k(const float* __restrict__ W1, const float* __restrict__ W2) {
    const int t1 = DIN * H1N;
    const int tot = t1 + H1N * H2N;
    for (int i = blockIdx.x * blockDim.x + threadIdx.x; i < tot;
         i += gridDim.x * blockDim.x) {
        if (i < t1) {
            int k = i / H1N, n = i % H1N;
            float v = W1[i];
            __nv_bfloat16 h = __float2bfloat16(v);
            __nv_bfloat16 l = __float2bfloat16(v - __bfloat162float(h));
            g_W1Th[n * DIN + k] = __bfloat16_as_ushort(h);
            g_W1Tl[n * DIN + k] = __bfloat16_as_ushort(l);
        } else {
            int j = i - t1;
            int k = j / H2N, n = j % H2N;
            float v = W2[j];
            __nv_bfloat16 h = __float2bfloat16(v);
            __nv_bfloat16 l = __float2bfloat16(v - __bfloat162float(h));
            g_W2Th[n * H1N + k] = __bfloat16_as_ushort(h);
            g_W2Tl[n * H1N + k] = __bfloat16_as_ushort(l);
        }
    }
}

__global__ void gather_fm_k(const int* __restrict__ xc,
                            const float* __restrict__ lin_tab,
                            const float* __restrict__ lat_tab,
                            const float* __restrict__ bias) {
    int row  = blockIdx.x * 8 + (threadIdx.x >> 5);
    int lane = threadIdx.x & 31;

    int   idx  = 0;
    float linv = 0.f;
    if (lane < NF) {
        idx  = xc[row * NF + lane];
        linv = lin_tab[lane * VOCAB + idx];
    }
    float sdim = 0.f, sq = 0.f;
    unsigned short* xh = &g_Xh[(size_t)row * DIN];
    unsigned short* xl = &g_Xl[(size_t)row * DIN];
#pragma unroll
    for (int f = 0; f < NF; ++f) {
        int id = __shfl_sync(0xffffffffu, idx, f);
        float e = lat_tab[((size_t)f * VOCAB + id) * ED + lane];
        __nv_bfloat16 h = __float2bfloat16(e);
        __nv_bfloat16 l = __float2bfloat16(e - __bfloat162float(h));
        xh[f * ED + lane] = __bfloat16_as_ushort(h);
        xl[f * ED + lane] = __bfloat16_as_ushort(l);
        sdim += e; sq += e * e;
    }
    float t = sdim * sdim - sq;
#pragma unroll
    for (int o = 16; o; o >>= 1) {
        t    += __shfl_xor_sync(0xffffffffu, t, o);
        linv += __shfl_xor_sync(0xffffffffu, linv, o);
    }
    if (lane == 0) g_fm[row] = linv + 0.5f * t + bias[0];
}

// ---- HMMA GEMM -------------------------------------------------------------
// C[B x NCOLS] = A[B x KTOT] @ Bt[NCOLS x KTOT]^T + bias, fused col stats.
// CTA tile TM x 128 (grid.y picks the 128-col slab). 256 threads = 8 warps
// (4m x 2n), warp tile (TM/4) x 64. A: 2 SMEM stages; B: 1 stage.
template<int KTOT, int NCOLS, int TM>
__global__ __launch_bounds__(256, 2)
void gemm_mma(const unsigned short* __restrict__ Ah,
              const unsigned short* __restrict__ Al,
              const unsigned short* __restrict__ Bh,
              const unsigned short* __restrict__ Bl,
              const float* __restrict__ bias, float* __restrict__ C,
              float* __restrict__ stats) {
    extern __shared__ char smem[];
    constexpr int STR    = 72;                 // halves per row (64 + 8 pad)
    constexpr int TILE_A = TM * STR * 2;       // bytes, one array
    constexpr int TILE_B = 128 * STR * 2;
    constexpr int OFF_B  = 4 * TILE_A;         // after 2 A stages (hi+lo each)
    constexpr int NCHUNK = KTOT / 64;
    constexpr int NMT    = TM / 64;            // 16-row blocks per warp (1|2)
    __shared__ float csum[128], csq[128];

    const uint32_t sb = smem_u32(smem);
    const int tid = threadIdx.x;
    const int lane = tid & 31;
    const int wid = tid >> 5;
    const int warp_m = wid & 3;
    const int warp_n = wid >> 2;
    const int rowBase = blockIdx.x * TM;
    const int colBase = blockIdx.y * 128;

    float acc[NMT][8][4];
#pragma unroll
    for (int i = 0; i < NMT; ++i)
#pragma unroll
        for (int j = 0; j < 8; ++j)
#pragma unroll
            for (int k = 0; k < 4; ++k) acc[i][j][k] = 0.f;

    const int a_row = warp_m * (TM / 4) + (lane & 15);
    const int a_col8 = (lane >> 4) << 3;
    const int b_row_base = warp_n * 64 + (lane & 7) + ((lane >> 4) << 3);
    const int b_col8 = ((lane >> 3) & 1) << 3;

    auto load_A = [&](int kc) {          // into A stage kc&1
        const uint32_t base = sb + (kc & 1) * (2 * TILE_A);
#pragma unroll
        for (int i = tid; i < TM * 8; i += 256) {
            int row = i >> 3, seg = i & 7;
            uint32_t soff = (uint32_t)(row * STR + seg * 8) * 2;
            size_t ga = (size_t)(rowBase + row) * KTOT + kc * 64 + seg * 8;
            cp16cg(base + soff,          Ah + ga);
            cp16cg(base + TILE_A + soff, Al + ga);
        }
        CP_COMMIT();
    };
    auto load_B = [&](int kc) {
#pragma unroll
        for (int i = tid; i < 128 * 8; i += 256) {
            int row = i >> 3, seg = i & 7;
            uint32_t soff = (uint32_t)(row * STR + seg * 8) * 2;
            size_t gb = (size_t)(colBase + row) * KTOT + kc * 64 + seg * 8;
            cp16ca(sb + OFF_B + soff,          Bh + gb);
            cp16ca(sb + OFF_B + TILE_B + soff, Bl + gb);
        }
        CP_COMMIT();
    };

    load_A(0);
    load_B(0);
    if (NCHUNK > 1) load_A(1);

    for (int kc = 0; kc < NCHUNK; ++kc) {
        if (kc + 1 < NCHUNK)
            asm volatile("cp.async.wait_group 1;" ::: "memory");
        else
            asm volatile("cp.async.wait_group 0;" ::: "memory");
        __syncthreads();

        const uint32_t baseA = sb + (kc & 1) * (2 * TILE_A);
#pragma unroll
        for (int ks = 0; ks < 4; ++ks) {
            uint32_t ah[NMT][4], al[NMT][4];
#pragma unroll
            for (int mt = 0; mt < NMT; ++mt) {
                uint32_t off = (uint32_t)((a_row + mt * 16) * STR +
                                          ks * 16 + a_col8) * 2;
                ldsm4(ah[mt], baseA + off);
                ldsm4(al[mt], baseA + TILE_A + off);
            }
            uint32_t bh[2][4], bl[2][4];
            {
                uint32_t off = (uint32_t)(b_row_base * STR + ks * 16 + b_col8) * 2;
                ldsm4(bh[0], sb + OFF_B + off);
                ldsm4(bl[0], sb + OFF_B + TILE_B + off);
            }
#pragma unroll
            for (int nb = 0; nb < 4; ++nb) {
                const int cur = nb & 1;
                if (nb < 3) {      // prefetch next B fragments over MMAs
                    uint32_t off = (uint32_t)((b_row_base + (nb + 1) * 16) * STR +
                                              ks * 16 + b_col8) * 2;
                    ldsm4(bh[cur ^ 1], sb + OFF_B + off);
                    ldsm4(bl[cur ^ 1], sb + OFF_B + TILE_B + off);
                }
#pragma unroll
                for (int mt = 0; mt < NMT; ++mt) {
                    mma16816(acc[mt][2 * nb],     ah[mt], bh[cur]);
                    mma16816(acc[mt][2 * nb],     ah[mt], bl[cur]);
                    mma16816(acc[mt][2 * nb],     al[mt], bh[cur]);
                    mma16816(acc[mt][2 * nb + 1], ah[mt], bh[cur] + 2);
                    mma16816(acc[mt][2 * nb + 1], ah[mt], bl[cur] + 2);
                    mma16816(acc[mt][2 * nb + 1], al[mt], bh[cur] + 2);
                }
            }
        }
        __syncthreads();
        if (kc + 1 < NCHUNK) {
            load_B(kc + 1);                       // B buffer now free
            if (kc + 2 < NCHUNK) load_A(kc + 2);  // A stage kc&1 now free
        }
    }

    // ---- epilogue: bias add, store, fused column stats ----
    if (tid < 128) { csum[tid] = 0.f; csq[tid] = 0.f; }
    __syncthreads();

#pragma unroll
    for (int nt = 0; nt < 8; ++nt) {
        int cl = warp_n * 64 + nt * 8 + 2 * (lane & 3);
        int c  = colBase + cl;
        float2 bv = *(const float2*)&bias[c];
        float s0 = 0.f, s1 = 0.f, q0 = 0.f, q1 = 0.f;
#pragma unroll
        for (int mt = 0; mt < NMT; ++mt) {
            int r0 = rowBase + warp_m * (TM / 4) + mt * 16 + (lane >> 2);
            float2 v0 = {acc[mt][nt][0] + bv.x, acc[mt][nt][1] + bv.y};
            float2 v1 = {acc[mt][nt][2] + bv.x, acc[mt][nt][3] + bv.y};
            *(float2*)&C[(size_t)r0 * NCOLS + c]       = v0;
            *(float2*)&C[(size_t)(r0 + 8) * NCOLS + c] = v1;
            s0 += v0.x + v1.x;  s1 += v0.y + v1.y;
            q0 += v0.x * v0.x + v1.x * v1.x;
            q1 += v0.y * v0.y + v1.y * v1.y;
        }
        atomicAdd(&csum[cl], s0);     atomicAdd(&csum[cl + 1], s1);
        atomicAdd(&csq[cl],  q0);     atomicAdd(&csq[cl + 1],  q1);
    }
    __syncthreads();
    if (tid < 128) {
        atomicAdd(&stats[colBase + tid],         csum[tid]);
        atomicAdd(&stats[NCOLS + colBase + tid], csq[tid]);
    }
}

// ---- BN prep, activation, final --------------------------------------------
__global__ void bn_prep_k(const float* __restrict__ g, const float* __restrict__ be) {
    int c = threadIdx.x;
    float s  = g_stats1[c];
    float sq = g_stats1[H1N + c];
    float mean = s * (1.f / BATCH);
    float var  = sq * (1.f / BATCH) - mean * mean;
    float rstd = rsqrtf(var + BN_EPS);
    float scl  = g[c] * rstd;
    g_sc1[c] = scl;
    g_sh1[c] = be[c] - mean * scl;
}

__global__ void act_k() {
    int q = blockIdx.x * blockDim.x + threadIdx.x;
    float4 v = ((const float4*)g_H1)[q];
    int c = (q * 4) & (H1N - 1);
    float h0 = fmaxf(fmaf(v.x, g_sc1[c + 0], g_sh1[c + 0]), 0.f);
    float h1 = fmaxf(fmaf(v.y, g_sc1[c + 1], g_sh1[c + 1]), 0.f);
    float h2 = fmaxf(fmaf(v.z, g_sc1[c + 2], g_sh1[c + 2]), 0.f);
    float h3 = fmaxf(fmaf(v.w, g_sc1[c + 3], g_sh1[c + 3]), 0.f);
    __nv_bfloat162 a = __floats2bfloat162_rn(h0, h1);
    __nv_bfloat162 b = __floats2bfloat162_rn(h2, h3);
    float l0 = h0 - __bfloat162float(a.x), l1 = h1 - __bfloat162float(a.y);
    float l2 = h2 - __bfloat162float(b.x), l3 = h3 - __bfloat162float(b.y);
    __nv_bfloat162 la = __floats2bfloat162_rn(l0, l1);
    __nv_bfloat162 lb = __floats2bfloat162_rn(l2, l3);
    uint2 uh = {*(uint32_t*)&a, *(uint32_t*)&b};
    uint2 ul = {*(uint32_t*)&la, *(uint32_t*)&lb};
    ((uint2*)g_A2h)[q] = uh;
    ((uint2*)g_A2l)[q] = ul;
}

__global__ void final_k(const float* __restrict__ W3, const float* __restrict__ b3,
                        const float* __restrict__ g2, const float* __restrict__ be2,
                        float* __restrict__ out) {
    __shared__ float sc[H2N], sh[H2N], w3s[H2N];
    int tid = threadIdx.x;
    if (tid < H2N) {
        float s  = g_stats2[tid];
        float sq = g_stats2[H2N + tid];
        float mean = s * (1.f / BATCH);
        float var  = sq * (1.f / BATCH) - mean * mean;
        float rstd = rsqrtf(var + BN_EPS);
        float scl  = g2[tid] * rstd;
        sc[tid] = scl;
        sh[tid] = be2[tid] - mean * scl;
        w3s[tid] = W3[tid];
    }
    __syncthreads();
    int warp = tid >> 5, lane = tid & 31;
    int row = blockIdx.x * 8 + warp;
    float acc = 0.f;
#pragma unroll
    for (int j = 0; j < 4; ++j) {
        int c = lane + j * 32;
        float v = g_H2[(size_t)row * H2N + c];
        acc += fmaxf(fmaf(v, sc[c], sh[c]), 0.f) * w3s[c];
    }
#pragma unroll
    for (int o = 16; o; o >>= 1) acc += __shfl_xor_sync(0xffffffffu, acc, o);
    if (lane == 0) out[row] = g_fm[row] + acc + b3[0];
}

// ---------------------------------------------------------------------------
extern "C" void kernel_launch(void* const* d_in, const int* in_sizes, int n_in,
                              void* d_out, int out_size) {
    const int*   xc   = (const int*)  d_in[0];
    const float* lin  = (const float*)d_in[1];
    const float* lat  = (const float*)d_in[2];
    const float* W1   = (const float*)d_in[3];
    const float* b1   = (const float*)d_in[4];
    const float* g1   = (const float*)d_in[5];
    const float* be1  = (const float*)d_in[6];
    const float* W2   = (const float*)d_in[7];
    const float* b2   = (const float*)d_in[8];
    const float* g2   = (const float*)d_in[9];
    const float* be2  = (const float*)d_in[10];
    const float* W3   = (const float*)d_in[11];
    const float* b3   = (const float*)d_in[12];
    const float* bias = (const float*)d_in[13];
    float* out = (float*)d_out;

    unsigned short *pXh, *pXl, *pA2h, *pA2l, *pW1h, *pW1l, *pW2h, *pW2l;
    float *pH1, *pH2, *pS1, *pS2;
    cudaGetSymbolAddress((void**)&pXh,  g_Xh);
    cudaGetSymbolAddress((void**)&pXl,  g_Xl);
    cudaGetSymbolAddress((void**)&pA2h, g_A2h);
    cudaGetSymbolAddress((void**)&pA2l, g_A2l);
    cudaGetSymbolAddress((void**)&pW1h, g_W1Th);
    cudaGetSymbolAddress((void**)&pW1l, g_W1Tl);
    cudaGetSymbolAddress((void**)&pW2h, g_W2Th);
    cudaGetSymbolAddress((void**)&pW2l, g_W2Tl);
    cudaGetSymbolAddress((void**)&pH1,  g_H1);
    cudaGetSymbolAddress((void**)&pH2,  g_H2);
    cudaGetSymbolAddress((void**)&pS1,  g_stats1);
    cudaGetSymbolAddress((void**)&pS2,  g_stats2);

    // SMEM: 4*TILE_A (2 A stages, hi+lo) + 2*TILE_B
    constexpr int SMEM1 = 4 * 128 * 72 * 2 + 2 * 128 * 72 * 2;  // 110592
    constexpr int SMEM2 = 4 *  64 * 72 * 2 + 2 * 128 * 72 * 2;  //  73728
    cudaFuncSetAttribute(gemm_mma<DIN, H1N, 128>,
                         cudaFuncAttributeMaxDynamicSharedMemorySize, SMEM1);
    cudaFuncSetAttribute(gemm_mma<H1N, H2N, 64>,
                         cudaFuncAttributeMaxDynamicSharedMemorySize, SMEM2);

    zero_stats_k<<<1, 256>>>();
    prep_w_k<<<480, 256>>>(W1, W2);
    gather_fm_k<<<BATCH / 8, 256>>>(xc, lin, lat, bias);
    gemm_mma<DIN, H1N, 128><<<dim3(BATCH / 128, H1N / 128), 256, SMEM1>>>(
        pXh, pXl, pW1h, pW1l, b1, pH1, pS1);
    bn_prep_k<<<1, H1N>>>(g1, be1);
    act_k<<<(BATCH * H1N / 4) / 256, 256>>>();
    gemm_mma<H1N, H2N, 64><<<dim3(BATCH / 64, H2N / 128), 256, SMEM2>>>(
        pA2h, pA2l, pW2h, pW2l, b2, pH2, pS2);
    final_k<<<BATCH / 8, 256>>>(W3, b3, g2, be2, out);
}

// round 8
// speedup vs baseline: 1.3091x; 1.3091x over previous
#include <cuda_runtime.h>
#include <cuda_fp16.h>
#include <cstdint>

// ---------------------------------------------------------------------------
// DeepFM forward — R8:
//   GEMM1: single-fp16 HMMA (1 MMA per k16 pair; error ~2^-12, OK vs 1e-3).
//   GEMM2: fp16 hi/lo 3-term split HMMA.
//   R4 macro shape (256 thr, 8 warps 4mx2n, k-chunk 64, single-buffer,
//   2 CTAs/SM). Column stats fused into GEMM epilogues.
//   B=16384, F=26, D=32, DIN=832, H1=256, H2=128, V=100000
// ---------------------------------------------------------------------------

#define BATCH  16384
#define NF     26
#define ED     32
#define DIN    832
#define H1N    256
#define H2N    128
#define VOCAB  100000
#define BN_EPS 1e-5f

// ---- scratch ---------------------------------------------------------------
__device__ unsigned short g_Xh[(size_t)BATCH * DIN];     // fp16 X
__device__ float          g_H1[(size_t)BATCH * H1N];
__device__ unsigned short g_A2h[(size_t)BATCH * H1N];    // fp16 act hi
__device__ unsigned short g_A2l[(size_t)BATCH * H1N];    // fp16 act lo
__device__ float          g_H2[(size_t)BATCH * H2N];
__device__ unsigned short g_W1T [H1N * DIN];             // fp16 W1^T
__device__ unsigned short g_W2Th[H2N * H1N], g_W2Tl[H2N * H1N];
__device__ float g_fm[BATCH];
__device__ float g_stats1[2 * H1N];
__device__ float g_stats2[2 * H2N];
__device__ float g_sc1[H1N], g_sh1[H1N];

// ---- PTX helpers -----------------------------------------------------------
__device__ __forceinline__ uint32_t smem_u32(const void* p) {
    uint32_t a;
    asm("{ .reg .u64 t; cvta.to.shared.u64 t, %1; cvt.u32.u64 %0, t; }"
        : "=r"(a) : "l"(p));
    return a;
}
__device__ __forceinline__ void cp16(uint32_t dst, const void* src) {
    asm volatile("cp.async.cg.shared.global [%0], [%1], 16;"
                 :: "r"(dst), "l"(src));
}
#define CP_COMMIT() asm volatile("cp.async.commit_group;" ::: "memory")
#define CP_WAIT0()  asm volatile("cp.async.wait_group 0;" ::: "memory")

__device__ __forceinline__ void ldsm4(uint32_t* r, uint32_t addr) {
    asm volatile("ldmatrix.sync.aligned.m8n8.x4.shared.b16 {%0,%1,%2,%3}, [%4];"
                 : "=r"(r[0]), "=r"(r[1]), "=r"(r[2]), "=r"(r[3]) : "r"(addr));
}
__device__ __forceinline__ void mma16816(float* d, const uint32_t* a,
                                         const uint32_t* b) {
    asm volatile(
        "mma.sync.aligned.m16n8k16.row.col.f32.f16.f16.f32 "
        "{%0,%1,%2,%3}, {%4,%5,%6,%7}, {%8,%9}, {%0,%1,%2,%3};"
        : "+f"(d[0]), "+f"(d[1]), "+f"(d[2]), "+f"(d[3])
        : "r"(a[0]), "r"(a[1]), "r"(a[2]), "r"(a[3]), "r"(b[0]), "r"(b[1]));
}

// ---- tiny kernels ----------------------------------------------------------
__global__ void zero_stats_k() {
    int t = threadIdx.x;
    g_stats1[t] = 0.f; g_stats1[H1N + t] = 0.f;
    if (t < H2N) { g_stats2[t] = 0.f; g_stats2[H2N + t] = 0.f; }
}

__global__ void prep_w_k(const float* __restrict__ W1, const float* __restrict__ W2) {
    const int t1 = DIN * H1N;
    const int tot = t1 + H1N * H2N;
    for (int i = blockIdx.x * blockDim.x + threadIdx.x; i < tot;
         i += gridDim.x * blockDim.x) {
        if (i < t1) {
            int k = i / H1N, n = i % H1N;
            g_W1T[n * DIN + k] = __half_as_ushort(__float2half(W1[i]));
        } else {
            int j = i - t1;
            int k = j / H2N, n = j % H2N;
            float v = W2[j];
            __half h = __float2half(v);
            __half l = __float2half(v - __half2float(h));
            g_W2Th[n * H1N + k] = __half_as_ushort(h);
            g_W2Tl[n * H1N + k] = __half_as_ushort(l);
        }
    }
}

// one warp per row: gather embeddings (fp16), FM logit
__global__ void gather_fm_k(const int* __restrict__ xc,
                            const float* __restrict__ lin_tab,
                            const float* __restrict__ lat_tab,
                            const float* __restrict__ bias) {
    int row  = blockIdx.x * 8 + (threadIdx.x >> 5);
    int lane = threadIdx.x & 31;

    int   idx  = 0;
    float linv = 0.f;
    if (lane < NF) {
        idx  = xc[row * NF + lane];
        linv = lin_tab[lane * VOCAB + idx];
    }
    float sdim = 0.f, sq = 0.f;
    unsigned short* xh = &g_Xh[(size_t)row * DIN];
#pragma unroll
    for (int f = 0; f < NF; ++f) {
        int id = __shfl_sync(0xffffffffu, idx, f);
        float e = lat_tab[((size_t)f * VOCAB + id) * ED + lane];
        xh[f * ED + lane] = __half_as_ushort(__float2half(e));
        sdim += e; sq += e * e;
    }
    float t = sdim * sdim - sq;
#pragma unroll
    for (int o = 16; o; o >>= 1) {
        t    += __shfl_xor_sync(0xffffffffu, t, o);
        linv += __shfl_xor_sync(0xffffffffu, linv, o);
    }
    if (lane == 0) g_fm[row] = linv + 0.5f * t + bias[0];
}

// ---- GEMM1: single fp16, R4 shape, fused stats -----------------------------
// C[B x NCOLS] = A[B x KTOT] @ Bt[NCOLS x KTOT]^T + bias.
template<int KTOT, int NCOLS>
__global__ __launch_bounds__(256, 2)
void gemm_fp16(const unsigned short* __restrict__ A,
               const unsigned short* __restrict__ Bt,
               const float* __restrict__ bias, float* __restrict__ C,
               float* __restrict__ stats) {
    extern __shared__ char smem[];
    constexpr int STR   = 72;
    constexpr int TILE  = 128 * STR * 2;       // one array, bytes
    constexpr int NCHUNK = KTOT / 64;
    __shared__ float csum[128], csq[128];

    const uint32_t sb = smem_u32(smem);
    const int tid = threadIdx.x;
    const int lane = tid & 31;
    const int wid = tid >> 5;
    const int warp_m = wid & 3;
    const int warp_n = wid >> 2;
    const int rowBase = blockIdx.x * 128;
    const int colBase = blockIdx.y * 128;

    float acc[2][8][4];
#pragma unroll
    for (int i = 0; i < 2; ++i)
#pragma unroll
        for (int j = 0; j < 8; ++j)
#pragma unroll
            for (int k = 0; k < 4; ++k) acc[i][j][k] = 0.f;

    const int a_row = warp_m * 32 + (lane & 15);
    const int a_col8 = (lane >> 4) << 3;
    const int b_row_base = warp_n * 64 + (lane & 7) + ((lane >> 4) << 3);
    const int b_col8 = ((lane >> 3) & 1) << 3;

    for (int kc = 0; kc < NCHUNK; ++kc) {
#pragma unroll
        for (int i = tid; i < 128 * 8; i += 256) {
            int row = i >> 3, seg = i & 7;
            uint32_t soff = (uint32_t)(row * STR + seg * 8) * 2;
            size_t ga = (size_t)(rowBase + row) * KTOT + kc * 64 + seg * 8;
            size_t gb = (size_t)(colBase + row) * KTOT + kc * 64 + seg * 8;
            cp16(sb + soff,        A + ga);
            cp16(sb + TILE + soff, Bt + gb);
        }
        CP_COMMIT();
        CP_WAIT0();
        __syncthreads();

#pragma unroll
        for (int ks = 0; ks < 4; ++ks) {
            uint32_t ah[2][4];
#pragma unroll
            for (int mt = 0; mt < 2; ++mt) {
                uint32_t off = (uint32_t)((a_row + mt * 16) * STR +
                                          ks * 16 + a_col8) * 2;
                ldsm4(ah[mt], sb + off);
            }
#pragma unroll
            for (int nb = 0; nb < 4; ++nb) {
                uint32_t bh[4];
                uint32_t off = (uint32_t)((b_row_base + nb * 16) * STR +
                                          ks * 16 + b_col8) * 2;
                ldsm4(bh, sb + TILE + off);
#pragma unroll
                for (int mt = 0; mt < 2; ++mt) {
                    mma16816(acc[mt][2 * nb],     ah[mt], bh);
                    mma16816(acc[mt][2 * nb + 1], ah[mt], bh + 2);
                }
            }
        }
        __syncthreads();
    }

    // epilogue: bias add, store, fused column stats
    if (tid < 128) { csum[tid] = 0.f; csq[tid] = 0.f; }
    __syncthreads();
#pragma unroll
    for (int nt = 0; nt < 8; ++nt) {
        int cl = warp_n * 64 + nt * 8 + 2 * (lane & 3);
        int c  = colBase + cl;
        float2 bv = *(const float2*)&bias[c];
        float s0 = 0.f, s1 = 0.f, q0 = 0.f, q1 = 0.f;
#pragma unroll
        for (int mt = 0; mt < 2; ++mt) {
            int r0 = rowBase + warp_m * 32 + mt * 16 + (lane >> 2);
            float2 v0 = {acc[mt][nt][0] + bv.x, acc[mt][nt][1] + bv.y};
            float2 v1 = {acc[mt][nt][2] + bv.x, acc[mt][nt][3] + bv.y};
            *(float2*)&C[(size_t)r0 * NCOLS + c]       = v0;
            *(float2*)&C[(size_t)(r0 + 8) * NCOLS + c] = v1;
            s0 += v0.x + v1.x;  s1 += v0.y + v1.y;
            q0 += v0.x * v0.x + v1.x * v1.x;
            q1 += v0.y * v0.y + v1.y * v1.y;
        }
        atomicAdd(&csum[cl], s0);     atomicAdd(&csum[cl + 1], s1);
        atomicAdd(&csq[cl],  q0);     atomicAdd(&csq[cl + 1],  q1);
    }
    __syncthreads();
    if (tid < 128) {
        atomicAdd(&stats[colBase + tid],         csum[tid]);
        atomicAdd(&stats[NCOLS + colBase + tid], csq[tid]);
    }
}

// ---- GEMM2: fp16 hi/lo 3-term split (R4 kernel), fused stats ---------------
template<int KTOT, int NCOLS>
__global__ __launch_bounds__(256, 2)
void gemm_split(const unsigned short* __restrict__ Ah,
                const unsigned short* __restrict__ Al,
                const unsigned short* __restrict__ Bh,
                const unsigned short* __restrict__ Bl,
                const float* __restrict__ bias, float* __restrict__ C,
                float* __restrict__ stats) {
    extern __shared__ char smem[];
    constexpr int STR = 72;
    constexpr int TILE = 128 * STR * 2;
    constexpr int OFF_AH = 0;
    constexpr int OFF_AL = TILE;
    constexpr int OFF_BH = 2 * TILE;
    constexpr int OFF_BL = 3 * TILE;
    constexpr int NCHUNK = KTOT / 64;
    __shared__ float csum[128], csq[128];

    const uint32_t sb = smem_u32(smem);
    const int tid = threadIdx.x;
    const int lane = tid & 31;
    const int wid = tid >> 5;
    const int warp_m = wid & 3;
    const int warp_n = wid >> 2;
    const int rowBase = blockIdx.x * 128;
    const int colBase = blockIdx.y * 128;

    float acc[2][8][4];
#pragma unroll
    for (int i = 0; i < 2; ++i)
#pragma unroll
        for (int j = 0; j < 8; ++j)
#pragma unroll
            for (int k = 0; k < 4; ++k) acc[i][j][k] = 0.f;

    const int a_row = warp_m * 32 + (lane & 15);
    const int a_col8 = (lane >> 4) << 3;
    const int b_row_base = warp_n * 64 + (lane & 7) + ((lane >> 4) << 3);
    const int b_col8 = ((lane >> 3) & 1) << 3;

    for (int kc = 0; kc < NCHUNK; ++kc) {
#pragma unroll
        for (int p = 0; p < 4; ++p) {
            int row = p * 32 + (tid >> 3);
            int seg = tid & 7;
            uint32_t soff = (uint32_t)(row * STR + seg * 8) * 2;
            size_t ga = (size_t)(rowBase + row) * KTOT + kc * 64 + seg * 8;
            size_t gb = (size_t)(colBase + row) * KTOT + kc * 64 + seg * 8;
            cp16(sb + OFF_AH + soff, Ah + ga);
            cp16(sb + OFF_AL + soff, Al + ga);
            cp16(sb + OFF_BH + soff, Bh + gb);
            cp16(sb + OFF_BL + soff, Bl + gb);
        }
        CP_COMMIT();
        CP_WAIT0();
        __syncthreads();

#pragma unroll
        for (int ks = 0; ks < 4; ++ks) {
            uint32_t ah[2][4], al[2][4];
#pragma unroll
            for (int mt = 0; mt < 2; ++mt) {
                uint32_t off = (uint32_t)((a_row + mt * 16) * STR +
                                          ks * 16 + a_col8) * 2;
                ldsm4(ah[mt], sb + OFF_AH + off);
                ldsm4(al[mt], sb + OFF_AL + off);
            }
#pragma unroll
            for (int nb = 0; nb < 4; ++nb) {
                uint32_t bh[4], bl[4];
                uint32_t off = (uint32_t)((b_row_base + nb * 16) * STR +
                                          ks * 16 + b_col8) * 2;
                ldsm4(bh, sb + OFF_BH + off);
                ldsm4(bl, sb + OFF_BL + off);
#pragma unroll
                for (int mt = 0; mt < 2; ++mt) {
                    mma16816(acc[mt][2 * nb],     ah[mt], bh);
                    mma16816(acc[mt][2 * nb],     ah[mt], bl);
                    mma16816(acc[mt][2 * nb],     al[mt], bh);
                    mma16816(acc[mt][2 * nb + 1], ah[mt], bh + 2);
                    mma16816(acc[mt][2 * nb + 1], ah[mt], bl + 2);
                    mma16816(acc[mt][2 * nb + 1], al[mt], bh + 2);
                }
            }
        }
        __syncthreads();
    }

    if (tid < 128) { csum[tid] = 0.f; csq[tid] = 0.f; }
    __syncthreads();
#pragma unroll
    for (int nt = 0; nt < 8; ++nt) {
        int cl = warp_n * 64 + nt * 8 + 2 * (lane & 3);
        int c  = colBase + cl;
        float2 bv = *(const float2*)&bias[c];
        float s0 = 0.f, s1 = 0.f, q0 = 0.f, q1 = 0.f;
#pragma unroll
        for (int mt = 0; mt < 2; ++mt) {
            int r0 = rowBase + warp_m * 32 + mt * 16 + (lane >> 2);
            float2 v0 = {acc[mt][nt][0] + bv.x, acc[mt][nt][1] + bv.y};
            float2 v1 = {acc[mt][nt][2] + bv.x, acc[mt][nt][3] + bv.y};
            *(float2*)&C[(size_t)r0 * NCOLS + c]       = v0;
            *(float2*)&C[(size_t)(r0 + 8) * NCOLS + c] = v1;
            s0 += v0.x + v1.x;  s1 += v0.y + v1.y;
            q0 += v0.x * v0.x + v1.x * v1.x;
            q1 += v0.y * v0.y + v1.y * v1.y;
        }
        atomicAdd(&csum[cl], s0);     atomicAdd(&csum[cl + 1], s1);
        atomicAdd(&csq[cl],  q0);     atomicAdd(&csq[cl + 1],  q1);
    }
    __syncthreads();
    if (tid < 128) {
        atomicAdd(&stats[colBase + tid],         csum[tid]);
        atomicAdd(&stats[NCOLS + colBase + tid], csq[tid]);
    }
}

// ---- BN prep, activation, final --------------------------------------------
__global__ void bn_prep_k(const float* __restrict__ g, const float* __restrict__ be) {
    int c = threadIdx.x;
    float s  = g_stats1[c];
    float sq = g_stats1[H1N + c];
    float mean = s * (1.f / BATCH);
    float var  = sq * (1.f / BATCH) - mean * mean;
    float rstd = rsqrtf(var + BN_EPS);
    float scl  = g[c] * rstd;
    g_sc1[c] = scl;
    g_sh1[c] = be[c] - mean * scl;
}

// relu(BN(H1)) -> fp16 hi/lo
__global__ void act_k() {
    int q = blockIdx.x * blockDim.x + threadIdx.x;
    float4 v = ((const float4*)g_H1)[q];
    int c = (q * 4) & (H1N - 1);
    float h0 = fmaxf(fmaf(v.x, g_sc1[c + 0], g_sh1[c + 0]), 0.f);
    float h1 = fmaxf(fmaf(v.y, g_sc1[c + 1], g_sh1[c + 1]), 0.f);
    float h2 = fmaxf(fmaf(v.z, g_sc1[c + 2], g_sh1[c + 2]), 0.f);
    float h3 = fmaxf(fmaf(v.w, g_sc1[c + 3], g_sh1[c + 3]), 0.f);
    __half2 a = __floats2half2_rn(h0, h1);
    __half2 b = __floats2half2_rn(h2, h3);
    float l0 = h0 - __half2float(a.x), l1 = h1 - __half2float(a.y);
    float l2 = h2 - __half2float(b.x), l3 = h3 - __half2float(b.y);
    __half2 la = __floats2half2_rn(l0, l1);
    __half2 lb = __floats2half2_rn(l2, l3);
    uint2 uh = {*(uint32_t*)&a, *(uint32_t*)&b};
    uint2 ul = {*(uint32_t*)&la, *(uint32_t*)&lb};
    ((uint2*)g_A2h)[q] = uh;
    ((uint2*)g_A2l)[q] = ul;
}

__global__ void final_k(const float* __restrict__ W3, const float* __restrict__ b3,
                        const float* __restrict__ g2, const float* __restrict__ be2,
                        float* __restrict__ out) {
    __shared__ float sc[H2N], sh[H2N], w3s[H2N];
    int tid = threadIdx.x;
    if (tid < H2N) {
        float s  = g_stats2[tid];
        float sq = g_stats2[H2N + tid];
        float mean = s * (1.f / BATCH);
        float var  = sq * (1.f / BATCH) - mean * mean;
        float rstd = rsqrtf(var + BN_EPS);
        float scl  = g2[tid] * rstd;
        sc[tid] = scl;
        sh[tid] = be2[tid] - mean * scl;
        w3s[tid] = W3[tid];
    }
    __syncthreads();
    int warp = tid >> 5, lane = tid & 31;
    int row = blockIdx.x * 8 + warp;
    float acc = 0.f;
#pragma unroll
    for (int j = 0; j < 4; ++j) {
        int c = lane + j * 32;
        float v = g_H2[(size_t)row * H2N + c];
        acc += fmaxf(fmaf(v, sc[c], sh[c]), 0.f) * w3s[c];
    }
#pragma unroll
    for (int o = 16; o; o >>= 1) acc += __shfl_xor_sync(0xffffffffu, acc, o);
    if (lane == 0) out[row] = g_fm[row] + acc + b3[0];
}

// ---------------------------------------------------------------------------
extern "C" void kernel_launch(void* const* d_in, const int* in_sizes, int n_in,
                              void* d_out, int out_size) {
    const int*   xc   = (const int*)  d_in[0];
    const float* lin  = (const float*)d_in[1];
    const float* lat  = (const float*)d_in[2];
    const float* W1   = (const float*)d_in[3];
    const float* b1   = (const float*)d_in[4];
    const float* g1   = (const float*)d_in[5];
    const float* be1  = (const float*)d_in[6];
    const float* W2   = (const float*)d_in[7];
    const float* b2   = (const float*)d_in[8];
    const float* g2   = (const float*)d_in[9];
    const float* be2  = (const float*)d_in[10];
    const float* W3   = (const float*)d_in[11];
    const float* b3   = (const float*)d_in[12];
    const float* bias = (const float*)d_in[13];
    float* out = (float*)d_out;

    unsigned short *pXh, *pA2h, *pA2l, *pW1, *pW2h, *pW2l;
    float *pH1, *pH2, *pS1, *pS2;
    cudaGetSymbolAddress((void**)&pXh,  g_Xh);
    cudaGetSymbolAddress((void**)&pA2h, g_A2h);
    cudaGetSymbolAddress((void**)&pA2l, g_A2l);
    cudaGetSymbolAddress((void**)&pW1,  g_W1T);
    cudaGetSymbolAddress((void**)&pW2h, g_W2Th);
    cudaGetSymbolAddress((void**)&pW2l, g_W2Tl);
    cudaGetSymbolAddress((void**)&pH1,  g_H1);
    cudaGetSymbolAddress((void**)&pH2,  g_H2);
    cudaGetSymbolAddress((void**)&pS1,  g_stats1);
    cudaGetSymbolAddress((void**)&pS2,  g_stats2);

    constexpr int SMEM1 = 2 * 128 * 72 * 2;   // 36864 (A + B, fp16 single)
    constexpr int SMEM2 = 4 * 128 * 72 * 2;   // 73728 (hi/lo both sides)
    cudaFuncSetAttribute(gemm_fp16<DIN, H1N>,
                         cudaFuncAttributeMaxDynamicSharedMemorySize, SMEM1);
    cudaFuncSetAttribute(gemm_split<H1N, H2N>,
                         cudaFuncAttributeMaxDynamicSharedMemorySize, SMEM2);

    zero_stats_k<<<1, 256>>>();
    prep_w_k<<<480, 256>>>(W1, W2);
    gather_fm_k<<<BATCH / 8, 256>>>(xc, lin, lat, bias);
    gemm_fp16<DIN, H1N><<<dim3(BATCH / 128, H1N / 128), 256, SMEM1>>>(
        pXh, pW1, b1, pH1, pS1);
    bn_prep_k<<<1, H1N>>>(g1, be1);
    act_k<<<(BATCH * H1N / 4) / 256, 256>>>();
    gemm_split<H1N, H2N><<<dim3(BATCH / 128, H2N / 128), 256, SMEM2>>>(
        pA2h, pA2l, pW2h, pW2l, b2, pH2, pS2);
    final_k<<<BATCH / 8, 256>>>(W3, b3, g2, be2, out);
}

// round 9
// speedup vs baseline: 1.4169x; 1.0824x over previous
#include <cuda_runtime.h>
#include <cuda_fp16.h>
#include <cstdint>

// ---------------------------------------------------------------------------
// DeepFM forward — R9:
//   GEMM1: single-fp16 HMMA, k-chunk 64, TRUE 2-stage double buffer,
//          2 CTAs/SM, fused column stats.
//   GEMM2: fp16 hi/lo 3-term split HMMA (R4 shape), fused column stats.
//   Launch fusion: pre = zero_stats + prep_w + gather_fm in one kernel;
//   act computes BN scale/shift per block (no bn_prep kernel).
//   5 launches total: pre, gemm1, act, gemm2, final.
//   B=16384, F=26, D=32, DIN=832, H1=256, H2=128, V=100000
// ---------------------------------------------------------------------------

#define BATCH  16384
#define NF     26
#define ED     32
#define DIN    832
#define H1N    256
#define H2N    128
#define VOCAB  100000
#define BN_EPS 1e-5f

// ---- scratch ---------------------------------------------------------------
__device__ unsigned short g_Xh[(size_t)BATCH * DIN];     // fp16 X
__device__ float          g_H1[(size_t)BATCH * H1N];
__device__ unsigned short g_A2h[(size_t)BATCH * H1N];    // fp16 act hi
__device__ unsigned short g_A2l[(size_t)BATCH * H1N];    // fp16 act lo
__device__ float          g_H2[(size_t)BATCH * H2N];
__device__ unsigned short g_W1T [H1N * DIN];             // fp16 W1^T
__device__ unsigned short g_W2Th[H2N * H1N], g_W2Tl[H2N * H1N];
__device__ float g_fm[BATCH];
__device__ float g_stats1[2 * H1N];
__device__ float g_stats2[2 * H2N];

// ---- PTX helpers -----------------------------------------------------------
__device__ __forceinline__ uint32_t smem_u32(const void* p) {
    uint32_t a;
    asm("{ .reg .u64 t; cvta.to.shared.u64 t, %1; cvt.u32.u64 %0, t; }"
        : "=r"(a) : "l"(p));
    return a;
}
__device__ __forceinline__ void cp16(uint32_t dst, const void* src) {
    asm volatile("cp.async.cg.shared.global [%0], [%1], 16;"
                 :: "r"(dst), "l"(src));
}
#define CP_COMMIT() asm volatile("cp.async.commit_group;" ::: "memory")

__device__ __forceinline__ void ldsm4(uint32_t* r, uint32_t addr) {
    asm volatile("ldmatrix.sync.aligned.m8n8.x4.shared.b16 {%0,%1,%2,%3}, [%4];"
                 : "=r"(r[0]), "=r"(r[1]), "=r"(r[2]), "=r"(r[3]) : "r"(addr));
}
__device__ __forceinline__ void mma16816(float* d, const uint32_t* a,
                                         const uint32_t* b) {
    asm volatile(
        "mma.sync.aligned.m16n8k16.row.col.f32.f16.f16.f32 "
        "{%0,%1,%2,%3}, {%4,%5,%6,%7}, {%8,%9}, {%0,%1,%2,%3};"
        : "+f"(d[0]), "+f"(d[1]), "+f"(d[2]), "+f"(d[3])
        : "r"(a[0]), "r"(a[1]), "r"(a[2]), "r"(a[3]), "r"(b[0]), "r"(b[1]));
}

// ---- fused pre kernel: zero stats | prep W | gather+FM ---------------------
// blocks [0, 2048)          : gather+FM (8 rows per block)
// blocks [2048, 2528)       : W1/W2 -> k-major fp16 (hi/lo for W2)
// block  2528               : zero stats
__global__ void pre_k(const int* __restrict__ xc,
                      const float* __restrict__ lin_tab,
                      const float* __restrict__ lat_tab,
                      const float* __restrict__ bias,
                      const float* __restrict__ W1,
                      const float* __restrict__ W2) {
    const int blk = blockIdx.x;
    const int tid = threadIdx.x;

    if (blk < 2048) {                       // ---- gather + FM ----
        int row  = blk * 8 + (tid >> 5);
        int lane = tid & 31;
        int   idx  = 0;
        float linv = 0.f;
        if (lane < NF) {
            idx  = xc[row * NF + lane];
            linv = lin_tab[lane * VOCAB + idx];
        }
        float sdim = 0.f, sq = 0.f;
        unsigned short* xh = &g_Xh[(size_t)row * DIN];
#pragma unroll
        for (int f = 0; f < NF; ++f) {
            int id = __shfl_sync(0xffffffffu, idx, f);
            float e = lat_tab[((size_t)f * VOCAB + id) * ED + lane];
            xh[f * ED + lane] = __half_as_ushort(__float2half(e));
            sdim += e; sq += e * e;
        }
        float t = sdim * sdim - sq;
#pragma unroll
        for (int o = 16; o; o >>= 1) {
            t    += __shfl_xor_sync(0xffffffffu, t, o);
            linv += __shfl_xor_sync(0xffffffffu, linv, o);
        }
        if (lane == 0) g_fm[row] = linv + 0.5f * t + bias[0];
    } else if (blk < 2528) {                // ---- weight prep ----
        const int t1 = DIN * H1N;
        const int tot = t1 + H1N * H2N;
        for (int i = (blk - 2048) * 256 + tid; i < tot; i += 480 * 256) {
            if (i < t1) {
                int k = i / H1N, n = i % H1N;
                g_W1T[n * DIN + k] = __half_as_ushort(__float2half(W1[i]));
            } else {
                int j = i - t1;
                int k = j / H2N, n = j % H2N;
                float v = W2[j];
                __half h = __float2half(v);
                __half l = __float2half(v - __half2float(h));
                g_W2Th[n * H1N + k] = __half_as_ushort(h);
                g_W2Tl[n * H1N + k] = __half_as_ushort(l);
            }
        }
    } else {                                // ---- zero stats ----
        g_stats1[tid] = 0.f; g_stats1[H1N + tid] = 0.f;
        if (tid < H2N) { g_stats2[tid] = 0.f; g_stats2[H2N + tid] = 0.f; }
    }
}

// ---- GEMM1: single fp16, 2-stage double buffer, fused stats ----------------
template<int KTOT, int NCOLS>
__global__ __launch_bounds__(256, 2)
void gemm_fp16(const unsigned short* __restrict__ A,
               const unsigned short* __restrict__ Bt,
               const float* __restrict__ bias, float* __restrict__ C,
               float* __restrict__ stats) {
    extern __shared__ char smem[];
    constexpr int STR    = 72;
    constexpr int TILE   = 128 * STR * 2;      // one array, bytes
    constexpr int STAGE  = 2 * TILE;           // A + B per stage
    constexpr int NCHUNK = KTOT / 64;
    __shared__ float csum[128], csq[128];

    const uint32_t sb = smem_u32(smem);
    const int tid = threadIdx.x;
    const int lane = tid & 31;
    const int wid = tid >> 5;
    const int warp_m = wid & 3;
    const int warp_n = wid >> 2;
    const int rowBase = blockIdx.x * 128;
    const int colBase = blockIdx.y * 128;

    float acc[2][8][4];
#pragma unroll
    for (int i = 0; i < 2; ++i)
#pragma unroll
        for (int j = 0; j < 8; ++j)
#pragma unroll
            for (int k = 0; k < 4; ++k) acc[i][j][k] = 0.f;

    const int a_row = warp_m * 32 + (lane & 15);
    const int a_col8 = (lane >> 4) << 3;
    const int b_row_base = warp_n * 64 + (lane & 7) + ((lane >> 4) << 3);
    const int b_col8 = ((lane >> 3) & 1) << 3;

    auto load_stage = [&](int kc) {
        const uint32_t base = sb + (kc & 1) * STAGE;
#pragma unroll
        for (int i = tid; i < 128 * 8; i += 256) {
            int row = i >> 3, seg = i & 7;
            uint32_t soff = (uint32_t)(row * STR + seg * 8) * 2;
            size_t ga = (size_t)(rowBase + row) * KTOT + kc * 64 + seg * 8;
            size_t gb = (size_t)(colBase + row) * KTOT + kc * 64 + seg * 8;
            cp16(base + soff,        A + ga);
            cp16(base + TILE + soff, Bt + gb);
        }
        CP_COMMIT();
    };

    load_stage(0);

    for (int kc = 0; kc < NCHUNK; ++kc) {
        if (kc + 1 < NCHUNK) {
            load_stage(kc + 1);
            asm volatile("cp.async.wait_group 1;" ::: "memory");
        } else {
            asm volatile("cp.async.wait_group 0;" ::: "memory");
        }
        __syncthreads();

        const uint32_t base = sb + (kc & 1) * STAGE;
#pragma unroll
        for (int ks = 0; ks < 4; ++ks) {
            uint32_t ah[2][4];
#pragma unroll
            for (int mt = 0; mt < 2; ++mt) {
                uint32_t off = (uint32_t)((a_row + mt * 16) * STR +
                                          ks * 16 + a_col8) * 2;
                ldsm4(ah[mt], base + off);
            }
#pragma unroll
            for (int nb = 0; nb < 4; ++nb) {
                uint32_t bh[4];
                uint32_t off = (uint32_t)((b_row_base + nb * 16) * STR +
                                          ks * 16 + b_col8) * 2;
                ldsm4(bh, base + TILE + off);
#pragma unroll
                for (int mt = 0; mt < 2; ++mt) {
                    mma16816(acc[mt][2 * nb],     ah[mt], bh);
                    mma16816(acc[mt][2 * nb + 1], ah[mt], bh + 2);
                }
            }
        }
        __syncthreads();
    }

    // epilogue: bias add, store, fused column stats
    if (tid < 128) { csum[tid] = 0.f; csq[tid] = 0.f; }
    __syncthreads();
#pragma unroll
    for (int nt = 0; nt < 8; ++nt) {
        int cl = warp_n * 64 + nt * 8 + 2 * (lane & 3);
        int c  = colBase + cl;
        float2 bv = *(const float2*)&bias[c];
        float s0 = 0.f, s1 = 0.f, q0 = 0.f, q1 = 0.f;
#pragma unroll
        for (int mt = 0; mt < 2; ++mt) {
            int r0 = rowBase + warp_m * 32 + mt * 16 + (lane >> 2);
            float2 v0 = {acc[mt][nt][0] + bv.x, acc[mt][nt][1] + bv.y};
            float2 v1 = {acc[mt][nt][2] + bv.x, acc[mt][nt][3] + bv.y};
            *(float2*)&C[(size_t)r0 * NCOLS + c]       = v0;
            *(float2*)&C[(size_t)(r0 + 8) * NCOLS + c] = v1;
            s0 += v0.x + v1.x;  s1 += v0.y + v1.y;
            q0 += v0.x * v0.x + v1.x * v1.x;
            q1 += v0.y * v0.y + v1.y * v1.y;
        }
        atomicAdd(&csum[cl], s0);     atomicAdd(&csum[cl + 1], s1);
        atomicAdd(&csq[cl],  q0);     atomicAdd(&csq[cl + 1],  q1);
    }
    __syncthreads();
    if (tid < 128) {
        atomicAdd(&stats[colBase + tid],         csum[tid]);
        atomicAdd(&stats[NCOLS + colBase + tid], csq[tid]);
    }
}

// ---- GEMM2: fp16 hi/lo 3-term split (R4 shape), fused stats ----------------
template<int KTOT, int NCOLS>
__global__ __launch_bounds__(256, 2)
void gemm_split(const unsigned short* __restrict__ Ah,
                const unsigned short* __restrict__ Al,
                const unsigned short* __restrict__ Bh,
                const unsigned short* __restrict__ Bl,
                const float* __restrict__ bias, float* __restrict__ C,
                float* __restrict__ stats) {
    extern __shared__ char smem[];
    constexpr int STR = 72;
    constexpr int TILE = 128 * STR * 2;
    constexpr int NCHUNK = KTOT / 64;
    __shared__ float csum[128], csq[128];

    const uint32_t sb = smem_u32(smem);
    const int tid = threadIdx.x;
    const int lane = tid & 31;
    const int wid = tid >> 5;
    const int warp_m = wid & 3;
    const int warp_n = wid >> 2;
    const int rowBase = blockIdx.x * 128;
    const int colBase = blockIdx.y * 128;

    float acc[2][8][4];
#pragma unroll
    for (int i = 0; i < 2; ++i)
#pragma unroll
        for (int j = 0; j < 8; ++j)
#pragma unroll
            for (int k = 0; k < 4; ++k) acc[i][j][k] = 0.f;

    const int a_row = warp_m * 32 + (lane & 15);
    const int a_col8 = (lane >> 4) << 3;
    const int b_row_base = warp_n * 64 + (lane & 7) + ((lane >> 4) << 3);
    const int b_col8 = ((lane >> 3) & 1) << 3;

    for (int kc = 0; kc < NCHUNK; ++kc) {
#pragma unroll
        for (int p = 0; p < 4; ++p) {
            int row = p * 32 + (tid >> 3);
            int seg = tid & 7;
            uint32_t soff = (uint32_t)(row * STR + seg * 8) * 2;
            size_t ga = (size_t)(rowBase + row) * KTOT + kc * 64 + seg * 8;
            size_t gb = (size_t)(colBase + row) * KTOT + kc * 64 + seg * 8;
            cp16(sb + soff,            Ah + ga);
            cp16(sb + TILE + soff,     Al + ga);
            cp16(sb + 2 * TILE + soff, Bh + gb);
            cp16(sb + 3 * TILE + soff, Bl + gb);
        }
        CP_COMMIT();
        asm volatile("cp.async.wait_group 0;" ::: "memory");
        __syncthreads();

#pragma unroll
        for (int ks = 0; ks < 4; ++ks) {
            uint32_t ah[2][4], al[2][4];
#pragma unroll
            for (int mt = 0; mt < 2; ++mt) {
                uint32_t off = (uint32_t)((a_row + mt * 16) * STR +
                                          ks * 16 + a_col8) * 2;
                ldsm4(ah[mt], sb + off);
                ldsm4(al[mt], sb + TILE + off);
            }
#pragma unroll
            for (int nb = 0; nb < 4; ++nb) {
                uint32_t bh[4], bl[4];
                uint32_t off = (uint32_t)((b_row_base + nb * 16) * STR +
                                          ks * 16 + b_col8) * 2;
                ldsm4(bh, sb + 2 * TILE + off);
                ldsm4(bl, sb + 3 * TILE + off);
#pragma unroll
                for (int mt = 0; mt < 2; ++mt) {
                    mma16816(acc[mt][2 * nb],     ah[mt], bh);
                    mma16816(acc[mt][2 * nb],     ah[mt], bl);
                    mma16816(acc[mt][2 * nb],     al[mt], bh);
                    mma16816(acc[mt][2 * nb + 1], ah[mt], bh + 2);
                    mma16816(acc[mt][2 * nb + 1], ah[mt], bl + 2);
                    mma16816(acc[mt][2 * nb + 1], al[mt], bh + 2);
                }
            }
        }
        __syncthreads();
    }

    if (tid < 128) { csum[tid] = 0.f; csq[tid] = 0.f; }
    __syncthreads();
#pragma unroll
    for (int nt = 0; nt < 8; ++nt) {
        int cl = warp_n * 64 + nt * 8 + 2 * (lane & 3);
        int c  = colBase + cl;
        float2 bv = *(const float2*)&bias[c];
        float s0 = 0.f, s1 = 0.f, q0 = 0.f, q1 = 0.f;
#pragma unroll
        for (int mt = 0; mt < 2; ++mt) {
            int r0 = rowBase + warp_m * 32 + mt * 16 + (lane >> 2);
            float2 v0 = {acc[mt][nt][0] + bv.x, acc[mt][nt][1] + bv.y};
            float2 v1 = {acc[mt][nt][2] + bv.x, acc[mt][nt][3] + bv.y};
            *(float2*)&C[(size_t)r0 * NCOLS + c]       = v0;
            *(float2*)&C[(size_t)(r0 + 8) * NCOLS + c] = v1;
            s0 += v0.x + v1.x;  s1 += v0.y + v1.y;
            q0 += v0.x * v0.x + v1.x * v1.x;
            q1 += v0.y * v0.y + v1.y * v1.y;
        }
        atomicAdd(&csum[cl], s0);     atomicAdd(&csum[cl + 1], s1);
        atomicAdd(&csq[cl],  q0);     atomicAdd(&csq[cl + 1],  q1);
    }
    __syncthreads();
    if (tid < 128) {
        atomicAdd(&stats[colBase + tid],         csum[tid]);
        atomicAdd(&stats[NCOLS + colBase + tid], csq[tid]);
    }
}

// ---- act: BN(scale/shift from stats) + ReLU -> fp16 hi/lo ------------------
__global__ void act_k(const float* __restrict__ g1, const float* __restrict__ be1) {
    __shared__ float sc[H1N], sh[H1N];
    const int tid = threadIdx.x;
    {
        float s  = g_stats1[tid];
        float sq = g_stats1[H1N + tid];
        float mean = s * (1.f / BATCH);
        float var  = sq * (1.f / BATCH) - mean * mean;
        float rstd = rsqrtf(var + BN_EPS);
        float scl  = g1[tid] * rstd;
        sc[tid] = scl;
        sh[tid] = be1[tid] - mean * scl;
    }
    __syncthreads();
    int q = blockIdx.x * 256 + tid;
    float4 v = ((const float4*)g_H1)[q];
    int c = (q * 4) & (H1N - 1);
    float h0 = fmaxf(fmaf(v.x, sc[c + 0], sh[c + 0]), 0.f);
    float h1 = fmaxf(fmaf(v.y, sc[c + 1], sh[c + 1]), 0.f);
    float h2 = fmaxf(fmaf(v.z, sc[c + 2], sh[c + 2]), 0.f);
    float h3 = fmaxf(fmaf(v.w, sc[c + 3], sh[c + 3]), 0.f);
    __half2 a = __floats2half2_rn(h0, h1);
    __half2 b = __floats2half2_rn(h2, h3);
    float l0 = h0 - __half2float(a.x), l1 = h1 - __half2float(a.y);
    float l2 = h2 - __half2float(b.x), l3 = h3 - __half2float(b.y);
    __half2 la = __floats2half2_rn(l0, l1);
    __half2 lb = __floats2half2_rn(l2, l3);
    uint2 uh = {*(uint32_t*)&a, *(uint32_t*)&b};
    uint2 ul = {*(uint32_t*)&la, *(uint32_t*)&lb};
    ((uint2*)g_A2h)[q] = uh;
    ((uint2*)g_A2l)[q] = ul;
}

// ---- final: out = fm + relu(BN(H2)) @ W3 + b3 ------------------------------
__global__ void final_k(const float* __restrict__ W3, const float* __restrict__ b3,
                        const float* __restrict__ g2, const float* __restrict__ be2,
                        float* __restrict__ out) {
    __shared__ float sc[H2N], sh[H2N], w3s[H2N];
    int tid = threadIdx.x;
    if (tid < H2N) {
        float s  = g_stats2[tid];
        float sq = g_stats2[H2N + tid];
        float mean = s * (1.f / BATCH);
        float var  = sq * (1.f / BATCH) - mean * mean;
        float rstd = rsqrtf(var + BN_EPS);
        float scl  = g2[tid] * rstd;
        sc[tid] = scl;
        sh[tid] = be2[tid] - mean * scl;
        w3s[tid] = W3[tid];
    }
    __syncthreads();
    int warp = tid >> 5, lane = tid & 31;
    int row = blockIdx.x * 8 + warp;
    float acc = 0.f;
#pragma unroll
    for (int j = 0; j < 4; ++j) {
        int c = lane + j * 32;
        float v = g_H2[(size_t)row * H2N + c];
        acc += fmaxf(fmaf(v, sc[c], sh[c]), 0.f) * w3s[c];
    }
#pragma unroll
    for (int o = 16; o; o >>= 1) acc += __shfl_xor_sync(0xffffffffu, acc, o);
    if (lane == 0) out[row] = g_fm[row] + acc + b3[0];
}

// ---------------------------------------------------------------------------
extern "C" void kernel_launch(void* const* d_in, const int* in_sizes, int n_in,
                              void* d_out, int out_size) {
    const int*   xc   = (const int*)  d_in[0];
    const float* lin  = (const float*)d_in[1];
    const float* lat  = (const float*)d_in[2];
    const float* W1   = (const float*)d_in[3];
    const float* b1   = (const float*)d_in[4];
    const float* g1   = (const float*)d_in[5];
    const float* be1  = (const float*)d_in[6];
    const float* W2   = (const float*)d_in[7];
    const float* b2   = (const float*)d_in[8];
    const float* g2   = (const float*)d_in[9];
    const float* be2  = (const float*)d_in[10];
    const float* W3   = (const float*)d_in[11];
    const float* b3   = (const float*)d_in[12];
    const float* bias = (const float*)d_in[13];
    float* out = (float*)d_out;

    unsigned short *pXh, *pA2h, *pA2l, *pW1, *pW2h, *pW2l;
    float *pH1, *pH2, *pS1, *pS2;
    cudaGetSymbolAddress((void**)&pXh,  g_Xh);
    cudaGetSymbolAddress((void**)&pA2h, g_A2h);
    cudaGetSymbolAddress((void**)&pA2l, g_A2l);
    cudaGetSymbolAddress((void**)&pW1,  g_W1T);
    cudaGetSymbolAddress((void**)&pW2h, g_W2Th);
    cudaGetSymbolAddress((void**)&pW2l, g_W2Tl);
    cudaGetSymbolAddress((void**)&pH1,  g_H1);
    cudaGetSymbolAddress((void**)&pH2,  g_H2);
    cudaGetSymbolAddress((void**)&pS1,  g_stats1);
    cudaGetSymbolAddress((void**)&pS2,  g_stats2);

    constexpr int SMEM1 = 2 * 2 * 128 * 72 * 2;   // 73728 (2 stages x (A+B))
    constexpr int SMEM2 = 4 * 128 * 72 * 2;       // 73728 (hi/lo both sides)
    cudaFuncSetAttribute(gemm_fp16<DIN, H1N>,
                         cudaFuncAttributeMaxDynamicSharedMemorySize, SMEM1);
    cudaFuncSetAttribute(gemm_split<H1N, H2N>,
                         cudaFuncAttributeMaxDynamicSharedMemorySize, SMEM2);

    pre_k<<<2529, 256>>>(xc, lin, lat, bias, W1, W2);
    gemm_fp16<DIN, H1N><<<dim3(BATCH / 128, H1N / 128), 256, SMEM1>>>(
        pXh, pW1, b1, pH1, pS1);
    act_k<<<(BATCH * H1N / 4) / 256, 256>>>(g1, be1);
    gemm_split<H1N, H2N><<<dim3(BATCH / 128, H2N / 128), 256, SMEM2>>>(
        pA2h, pA2l, pW2h, pW2l, b2, pH2, pS2);
    final_k<<<BATCH / 8, 256>>>(W3, b3, g2, be2, out);
}

// round 11
// speedup vs baseline: 1.5091x; 1.0651x over previous
#include <cuda_runtime.h>
#include <cuda_fp16.h>
#include <cstdint>

// ---------------------------------------------------------------------------
// DeepFM forward — R11 (= R10 with the gemm2 SMEM race fixed):
//   GEMM1: single-fp16 HMMA, k64, 2-stage double buffer, 2 CTAs/SM,
//          fused column stats (R9, proven).
//   GEMM2: TM=64 tile (grid 256 -> 2 CTAs/SM), BN+ReLU+fp16-split fused
//          into the A path; ALL SMEM writes strictly after the sync that
//          retires the previous chunk's reads.
//   4 launches: pre, gemm1, gemm2, final.
//   B=16384, F=26, D=32, DIN=832, H1=256, H2=128, V=100000
// ---------------------------------------------------------------------------

#define BATCH  16384
#define NF     26
#define ED     32
#define DIN    832
#define H1N    256
#define H2N    128
#define VOCAB  100000
#define BN_EPS 1e-5f

// ---- scratch ---------------------------------------------------------------
__device__ unsigned short g_Xh[(size_t)BATCH * DIN];     // fp16 X
__device__ float          g_H1[(size_t)BATCH * H1N];
__device__ float          g_H2[(size_t)BATCH * H2N];
__device__ unsigned short g_W1T [H1N * DIN];             // fp16 W1^T
__device__ unsigned short g_W2Th[H2N * H1N], g_W2Tl[H2N * H1N];
__device__ float g_fm[BATCH];
__device__ float g_stats1[2 * H1N];
__device__ float g_stats2[2 * H2N];

// ---- PTX helpers -----------------------------------------------------------
__device__ __forceinline__ uint32_t smem_u32(const void* p) {
    uint32_t a;
    asm("{ .reg .u64 t; cvta.to.shared.u64 t, %1; cvt.u32.u64 %0, t; }"
        : "=r"(a) : "l"(p));
    return a;
}
__device__ __forceinline__ void cp16(uint32_t dst, const void* src) {
    asm volatile("cp.async.cg.shared.global [%0], [%1], 16;"
                 :: "r"(dst), "l"(src));
}
#define CP_COMMIT() asm volatile("cp.async.commit_group;" ::: "memory")

__device__ __forceinline__ void ldsm4(uint32_t* r, uint32_t addr) {
    asm volatile("ldmatrix.sync.aligned.m8n8.x4.shared.b16 {%0,%1,%2,%3}, [%4];"
                 : "=r"(r[0]), "=r"(r[1]), "=r"(r[2]), "=r"(r[3]) : "r"(addr));
}
__device__ __forceinline__ void mma16816(float* d, const uint32_t* a,
                                         const uint32_t* b) {
    asm volatile(
        "mma.sync.aligned.m16n8k16.row.col.f32.f16.f16.f32 "
        "{%0,%1,%2,%3}, {%4,%5,%6,%7}, {%8,%9}, {%0,%1,%2,%3};"
        : "+f"(d[0]), "+f"(d[1]), "+f"(d[2]), "+f"(d[3])
        : "r"(a[0]), "r"(a[1]), "r"(a[2]), "r"(a[3]), "r"(b[0]), "r"(b[1]));
}

// ---- fused pre kernel: zero stats | prep W | gather+FM ---------------------
__global__ void pre_k(const int* __restrict__ xc,
                      const float* __restrict__ lin_tab,
                      const float* __restrict__ lat_tab,
                      const float* __restrict__ bias,
                      const float* __restrict__ W1,
                      const float* __restrict__ W2) {
    const int blk = blockIdx.x;
    const int tid = threadIdx.x;

    if (blk < 2048) {                       // ---- gather + FM ----
        int row  = blk * 8 + (tid >> 5);
        int lane = tid & 31;
        int   idx  = 0;
        float linv = 0.f;
        if (lane < NF) {
            idx  = xc[row * NF + lane];
            linv = lin_tab[lane * VOCAB + idx];
        }
        float sdim = 0.f, sq = 0.f;
        unsigned short* xh = &g_Xh[(size_t)row * DIN];
#pragma unroll
        for (int f = 0; f < NF; ++f) {
            int id = __shfl_sync(0xffffffffu, idx, f);
            float e = lat_tab[((size_t)f * VOCAB + id) * ED + lane];
            xh[f * ED + lane] = __half_as_ushort(__float2half(e));
            sdim += e; sq += e * e;
        }
        float t = sdim * sdim - sq;
#pragma unroll
        for (int o = 16; o; o >>= 1) {
            t    += __shfl_xor_sync(0xffffffffu, t, o);
            linv += __shfl_xor_sync(0xffffffffu, linv, o);
        }
        if (lane == 0) g_fm[row] = linv + 0.5f * t + bias[0];
    } else if (blk < 2528) {                // ---- weight prep ----
        const int t1 = DIN * H1N;
        const int tot = t1 + H1N * H2N;
        for (int i = (blk - 2048) * 256 + tid; i < tot; i += 480 * 256) {
            if (i < t1) {
                int k = i / H1N, n = i % H1N;
                g_W1T[n * DIN + k] = __half_as_ushort(__float2half(W1[i]));
            } else {
                int j = i - t1;
                int k = j / H2N, n = j % H2N;
                float v = W2[j];
                __half h = __float2half(v);
                __half l = __float2half(v - __half2float(h));
                g_W2Th[n * H1N + k] = __half_as_ushort(h);
                g_W2Tl[n * H1N + k] = __half_as_ushort(l);
            }
        }
    } else {                                // ---- zero stats ----
        g_stats1[tid] = 0.f; g_stats1[H1N + tid] = 0.f;
        if (tid < H2N) { g_stats2[tid] = 0.f; g_stats2[H2N + tid] = 0.f; }
    }
}

// ---- GEMM1: single fp16, 2-stage double buffer, fused stats (R9) -----------
template<int KTOT, int NCOLS>
__global__ __launch_bounds__(256, 2)
void gemm_fp16(const unsigned short* __restrict__ A,
               const unsigned short* __restrict__ Bt,
               const float* __restrict__ bias, float* __restrict__ C,
               float* __restrict__ stats) {
    extern __shared__ char smem[];
    constexpr int STR    = 72;
    constexpr int TILE   = 128 * STR * 2;
    constexpr int STAGE  = 2 * TILE;
    constexpr int NCHUNK = KTOT / 64;
    __shared__ float csum[128], csq[128];

    const uint32_t sb = smem_u32(smem);
    const int tid = threadIdx.x;
    const int lane = tid & 31;
    const int wid = tid >> 5;
    const int warp_m = wid & 3;
    const int warp_n = wid >> 2;
    const int rowBase = blockIdx.x * 128;
    const int colBase = blockIdx.y * 128;

    float acc[2][8][4];
#pragma unroll
    for (int i = 0; i < 2; ++i)
#pragma unroll
        for (int j = 0; j < 8; ++j)
#pragma unroll
            for (int k = 0; k < 4; ++k) acc[i][j][k] = 0.f;

    const int a_row = warp_m * 32 + (lane & 15);
    const int a_col8 = (lane >> 4) << 3;
    const int b_row_base = warp_n * 64 + (lane & 7) + ((lane >> 4) << 3);
    const int b_col8 = ((lane >> 3) & 1) << 3;

    auto load_stage = [&](int kc) {
        const uint32_t base = sb + (kc & 1) * STAGE;
#pragma unroll
        for (int i = tid; i < 128 * 8; i += 256) {
            int row = i >> 3, seg = i & 7;
            uint32_t soff = (uint32_t)(row * STR + seg * 8) * 2;
            size_t ga = (size_t)(rowBase + row) * KTOT + kc * 64 + seg * 8;
            size_t gb = (size_t)(colBase + row) * KTOT + kc * 64 + seg * 8;
            cp16(base + soff,        A + ga);
            cp16(base + TILE + soff, Bt + gb);
        }
        CP_COMMIT();
    };

    load_stage(0);

    for (int kc = 0; kc < NCHUNK; ++kc) {
        if (kc + 1 < NCHUNK) {
            load_stage(kc + 1);
            asm volatile("cp.async.wait_group 1;" ::: "memory");
        } else {
            asm volatile("cp.async.wait_group 0;" ::: "memory");
        }
        __syncthreads();

        const uint32_t base = sb + (kc & 1) * STAGE;
#pragma unroll
        for (int ks = 0; ks < 4; ++ks) {
            uint32_t ah[2][4];
#pragma unroll
            for (int mt = 0; mt < 2; ++mt) {
                uint32_t off = (uint32_t)((a_row + mt * 16) * STR +
                                          ks * 16 + a_col8) * 2;
                ldsm4(ah[mt], base + off);
            }
#pragma unroll
            for (int nb = 0; nb < 4; ++nb) {
                uint32_t bh[4];
                uint32_t off = (uint32_t)((b_row_base + nb * 16) * STR +
                                          ks * 16 + b_col8) * 2;
                ldsm4(bh, base + TILE + off);
#pragma unroll
                for (int mt = 0; mt < 2; ++mt) {
                    mma16816(acc[mt][2 * nb],     ah[mt], bh);
                    mma16816(acc[mt][2 * nb + 1], ah[mt], bh + 2);
                }
            }
        }
        __syncthreads();
    }

    if (tid < 128) { csum[tid] = 0.f; csq[tid] = 0.f; }
    __syncthreads();
#pragma unroll
    for (int nt = 0; nt < 8; ++nt) {
        int cl = warp_n * 64 + nt * 8 + 2 * (lane & 3);
        int c  = colBase + cl;
        float2 bv = *(const float2*)&bias[c];
        float s0 = 0.f, s1 = 0.f, q0 = 0.f, q1 = 0.f;
#pragma unroll
        for (int mt = 0; mt < 2; ++mt) {
            int r0 = rowBase + warp_m * 32 + mt * 16 + (lane >> 2);
            float2 v0 = {acc[mt][nt][0] + bv.x, acc[mt][nt][1] + bv.y};
            float2 v1 = {acc[mt][nt][2] + bv.x, acc[mt][nt][3] + bv.y};
            *(float2*)&C[(size_t)r0 * NCOLS + c]       = v0;
            *(float2*)&C[(size_t)(r0 + 8) * NCOLS + c] = v1;
            s0 += v0.x + v1.x;  s1 += v0.y + v1.y;
            q0 += v0.x * v0.x + v1.x * v1.x;
            q1 += v0.y * v0.y + v1.y * v1.y;
        }
        atomicAdd(&csum[cl], s0);     atomicAdd(&csum[cl + 1], s1);
        atomicAdd(&csq[cl],  q0);     atomicAdd(&csq[cl + 1],  q1);
    }
    __syncthreads();
    if (tid < 128) {
        atomicAdd(&stats[colBase + tid],         csum[tid]);
        atomicAdd(&stats[NCOLS + colBase + tid], csq[tid]);
    }
}

// ---- GEMM2: TM=64, act fused into A path, fp16 hi/lo split, fused stats ----
// H2[B x 128] = relu(BN(H1))[B x 256] @ W2t[128 x 256]^T + b2
// Per chunk: A reg-prefetch (global, overlaps prev compute) -> sync ->
//            B cp.async + A convert/store -> wait + sync -> compute.
__global__ __launch_bounds__(256, 2)
void gemm2_k(const float* __restrict__ H1,
             const unsigned short* __restrict__ Bh,
             const unsigned short* __restrict__ Bl,
             const float* __restrict__ g1, const float* __restrict__ be1,
             const float* __restrict__ bias, float* __restrict__ C,
             float* __restrict__ stats) {
    extern __shared__ char smem[];
    constexpr int KTOT = H1N, NCOLS = H2N;
    constexpr int STR = 72;
    constexpr int TILE_A = 64 * STR * 2;        // bytes (one of hi/lo)
    constexpr int TILE_B = 128 * STR * 2;
    constexpr int OFF_B  = 2 * TILE_A;
    constexpr int NCHUNK = KTOT / 64;           // 4
    __shared__ float sc[H1N], sh[H1N];
    __shared__ float csum[128], csq[128];

    const uint32_t sb = smem_u32(smem);
    const int tid = threadIdx.x;
    const int lane = tid & 31;
    const int wid = tid >> 5;
    const int warp_m = wid & 3;
    const int warp_n = wid >> 2;
    const int rowBase = blockIdx.x * 64;

    {   // BN scale/shift from global stats1
        float s  = g_stats1[tid];
        float sq = g_stats1[H1N + tid];
        float mean = s * (1.f / BATCH);
        float var  = sq * (1.f / BATCH) - mean * mean;
        float rstd = rsqrtf(var + BN_EPS);
        float scl  = g1[tid] * rstd;
        sc[tid] = scl;
        sh[tid] = be1[tid] - mean * scl;
    }
    __syncthreads();

    float acc[8][4];
#pragma unroll
    for (int j = 0; j < 8; ++j)
#pragma unroll
        for (int k = 0; k < 4; ++k) acc[j][k] = 0.f;

    const int a_row = warp_m * 16 + (lane & 15);
    const int a_col8 = (lane >> 4) << 3;
    const int b_row_base = warp_n * 64 + (lane & 7) + ((lane >> 4) << 3);
    const int b_col8 = ((lane >> 3) & 1) << 3;

    const int al_row = tid >> 2;          // 0..63
    const int al_seg = tid & 3;           // 0..3

    for (int kc = 0; kc < NCHUNK; ++kc) {
        // A register prefetch (global; overlaps previous chunk's compute)
        float4 ra[4];
#pragma unroll
        for (int p = 0; p < 4; ++p) {
            int kk = kc * 64 + (al_seg + p * 4) * 4;
            ra[p] = *(const float4*)&H1[(size_t)(rowBase + al_row) * KTOT + kk];
        }

        __syncthreads();   // ALL warps done reading SMEM from previous chunk

        // B via cp.async (safe now)
#pragma unroll
        for (int i = tid; i < 128 * 8; i += 256) {
            int row = i >> 3, seg = i & 7;
            uint32_t soff = (uint32_t)(row * STR + seg * 8) * 2;
            size_t gb = (size_t)row * KTOT + kc * 64 + seg * 8;
            cp16(sb + OFF_B + soff,          Bh + gb);
            cp16(sb + OFF_B + TILE_B + soff, Bl + gb);
        }
        CP_COMMIT();

        // BN + ReLU + hi/lo split -> A SMEM (safe now)
#pragma unroll
        for (int p = 0; p < 4; ++p) {
            int kk = kc * 64 + (al_seg + p * 4) * 4;
            int cl = kk & (H1N - 1);
            float h0 = fmaxf(fmaf(ra[p].x, sc[cl + 0], sh[cl + 0]), 0.f);
            float h1 = fmaxf(fmaf(ra[p].y, sc[cl + 1], sh[cl + 1]), 0.f);
            float h2 = fmaxf(fmaf(ra[p].z, sc[cl + 2], sh[cl + 2]), 0.f);
            float h3 = fmaxf(fmaf(ra[p].w, sc[cl + 3], sh[cl + 3]), 0.f);
            __half2 a = __floats2half2_rn(h0, h1);
            __half2 b = __floats2half2_rn(h2, h3);
            __half2 la = __floats2half2_rn(h0 - __half2float(a.x),
                                           h1 - __half2float(a.y));
            __half2 lb = __floats2half2_rn(h2 - __half2float(b.x),
                                           h3 - __half2float(b.y));
            uint32_t soff = (uint32_t)(al_row * STR + (al_seg + p * 4) * 4) * 2;
            *(uint32_t*)(smem + soff)              = *(uint32_t*)&a;
            *(uint32_t*)(smem + soff + 4)          = *(uint32_t*)&b;
            *(uint32_t*)(smem + TILE_A + soff)     = *(uint32_t*)&la;
            *(uint32_t*)(smem + TILE_A + soff + 4) = *(uint32_t*)&lb;
        }
        asm volatile("cp.async.wait_group 0;" ::: "memory");
        __syncthreads();

#pragma unroll
        for (int ks = 0; ks < 4; ++ks) {
            uint32_t ah[4], al[4];
            {
                uint32_t off = (uint32_t)(a_row * STR + ks * 16 + a_col8) * 2;
                ldsm4(ah, sb + off);
                ldsm4(al, sb + TILE_A + off);
            }
#pragma unroll
            for (int nb = 0; nb < 4; ++nb) {
                uint32_t bh[4], bl[4];
                uint32_t off = (uint32_t)((b_row_base + nb * 16) * STR +
                                          ks * 16 + b_col8) * 2;
                ldsm4(bh, sb + OFF_B + off);
                ldsm4(bl, sb + OFF_B + TILE_B + off);
                mma16816(acc[2 * nb],     ah, bh);
                mma16816(acc[2 * nb],     ah, bl);
                mma16816(acc[2 * nb],     al, bh);
                mma16816(acc[2 * nb + 1], ah, bh + 2);
                mma16816(acc[2 * nb + 1], ah, bl + 2);
                mma16816(acc[2 * nb + 1], al, bh + 2);
            }
        }
    }
    __syncthreads();

    // epilogue: bias add, store, fused column stats
    if (tid < 128) { csum[tid] = 0.f; csq[tid] = 0.f; }
    __syncthreads();
#pragma unroll
    for (int nt = 0; nt < 8; ++nt) {
        int cl = warp_n * 64 + nt * 8 + 2 * (lane & 3);
        float2 bv = *(const float2*)&bias[cl];
        int r0 = rowBase + warp_m * 16 + (lane >> 2);
        float2 v0 = {acc[nt][0] + bv.x, acc[nt][1] + bv.y};
        float2 v1 = {acc[nt][2] + bv.x, acc[nt][3] + bv.y};
        *(float2*)&C[(size_t)r0 * NCOLS + cl]       = v0;
        *(float2*)&C[(size_t)(r0 + 8) * NCOLS + cl] = v1;
        atomicAdd(&csum[cl],     v0.x + v1.x);
        atomicAdd(&csum[cl + 1], v0.y + v1.y);
        atomicAdd(&csq[cl],      v0.x * v0.x + v1.x * v1.x);
        atomicAdd(&csq[cl + 1],  v0.y * v0.y + v1.y * v1.y);
    }
    __syncthreads();
    if (tid < 128) {
        atomicAdd(&stats[tid],         csum[tid]);
        atomicAdd(&stats[NCOLS + tid], csq[tid]);
    }
}

// ---- final: out = fm + relu(BN(H2)) @ W3 + b3 ------------------------------
__global__ void final_k(const float* __restrict__ W3, const float* __restrict__ b3,
                        const float* __restrict__ g2, const float* __restrict__ be2,
                        float* __restrict__ out) {
    __shared__ float sc[H2N], sh[H2N], w3s[H2N];
    int tid = threadIdx.x;
    if (tid < H2N) {
        float s  = g_stats2[tid];
        float sq = g_stats2[H2N + tid];
        float mean = s * (1.f / BATCH);
        float var  = sq * (1.f / BATCH) - mean * mean;
        float rstd = rsqrtf(var + BN_EPS);
        float scl  = g2[tid] * rstd;
        sc[tid] = scl;
        sh[tid] = be2[tid] - mean * scl;
        w3s[tid] = W3[tid];
    }
    __syncthreads();
    int warp = tid >> 5, lane = tid & 31;
    int row = blockIdx.x * 8 + warp;
    float acc = 0.f;
#pragma unroll
    for (int j = 0; j < 4; ++j) {
        int c = lane + j * 32;
        float v = g_H2[(size_t)row * H2N + c];
        acc += fmaxf(fmaf(v, sc[c], sh[c]), 0.f) * w3s[c];
    }
#pragma unroll
    for (int o = 16; o; o >>= 1) acc += __shfl_xor_sync(0xffffffffu, acc, o);
    if (lane == 0) out[row] = g_fm[row] + acc + b3[0];
}

// ---------------------------------------------------------------------------
extern "C" void kernel_launch(void* const* d_in, const int* in_sizes, int n_in,
                              void* d_out, int out_size) {
    const int*   xc   = (const int*)  d_in[0];
    const float* lin  = (const float*)d_in[1];
    const float* lat  = (const float*)d_in[2];
    const float* W1   = (const float*)d_in[3];
    const float* b1   = (const float*)d_in[4];
    const float* g1   = (const float*)d_in[5];
    const float* be1  = (const float*)d_in[6];
    const float* W2   = (const float*)d_in[7];
    const float* b2   = (const float*)d_in[8];
    const float* g2   = (const float*)d_in[9];
    const float* be2  = (const float*)d_in[10];
    const float* W3   = (const float*)d_in[11];
    const float* b3   = (const float*)d_in[12];
    const float* bias = (const float*)d_in[13];
    float* out = (float*)d_out;

    unsigned short *pXh, *pW1, *pW2h, *pW2l;
    float *pH1, *pH2, *pS1, *pS2;
    cudaGetSymbolAddress((void**)&pXh,  g_Xh);
    cudaGetSymbolAddress((void**)&pW1,  g_W1T);
    cudaGetSymbolAddress((void**)&pW2h, g_W2Th);
    cudaGetSymbolAddress((void**)&pW2l, g_W2Tl);
    cudaGetSymbolAddress((void**)&pH1,  g_H1);
    cudaGetSymbolAddress((void**)&pH2,  g_H2);
    cudaGetSymbolAddress((void**)&pS1,  g_stats1);
    cudaGetSymbolAddress((void**)&pS2,  g_stats2);

    constexpr int SMEM1 = 2 * 2 * 128 * 72 * 2;                // 73728
    constexpr int SMEM2 = 2 * 64 * 72 * 2 + 2 * 128 * 72 * 2;  // 55296
    cudaFuncSetAttribute(gemm_fp16<DIN, H1N>,
                         cudaFuncAttributeMaxDynamicSharedMemorySize, SMEM1);
    cudaFuncSetAttribute(gemm2_k,
                         cudaFuncAttributeMaxDynamicSharedMemorySize, SMEM2);

    pre_k<<<2529, 256>>>(xc, lin, lat, bias, W1, W2);
    gemm_fp16<DIN, H1N><<<dim3(BATCH / 128, H1N / 128), 256, SMEM1>>>(
        pXh, pW1, b1, pH1, pS1);
    gemm2_k<<<BATCH / 64, 256, SMEM2>>>(pH1, pW2h, pW2l, g1, be1, b2, pH2, pS2);
    final_k<<<BATCH / 8, 256>>>(W3, b3, g2, be2, out);
}

// round 12
// speedup vs baseline: 1.6003x; 1.0604x over previous
#include <cuda_runtime.h>
#include <cuda_fp16.h>
#include <cstdint>

// ---------------------------------------------------------------------------
// DeepFM forward — R12:
//   GEMM1: single-fp16 HMMA, k64, 2-stage double buffer, 2 CTAs/SM,
//          fused column stats (R9/R11, proven; untouched).
//   GEMM2: SINGLE fp16 (split dropped), TM=64, 2-stage double buffer in the
//          proven gemm1 ordering; BN+ReLU+fp16 convert fused into the A path
//          (A regs ldg one chunk ahead); fused column stats.
//   4 launches: pre, gemm1, gemm2, final.
//   B=16384, F=26, D=32, DIN=832, H1=256, H2=128, V=100000
// ---------------------------------------------------------------------------

#define BATCH  16384
#define NF     26
#define ED     32
#define DIN    832
#define H1N    256
#define H2N    128
#define VOCAB  100000
#define BN_EPS 1e-5f

// ---- scratch ---------------------------------------------------------------
__device__ unsigned short g_Xh[(size_t)BATCH * DIN];     // fp16 X
__device__ float          g_H1[(size_t)BATCH * H1N];
__device__ float          g_H2[(size_t)BATCH * H2N];
__device__ unsigned short g_W1T[H1N * DIN];              // fp16 W1^T
__device__ unsigned short g_W2T[H2N * H1N];              // fp16 W2^T
__device__ float g_fm[BATCH];
__device__ float g_stats1[2 * H1N];
__device__ float g_stats2[2 * H2N];

// ---- PTX helpers -----------------------------------------------------------
__device__ __forceinline__ uint32_t smem_u32(const void* p) {
    uint32_t a;
    asm("{ .reg .u64 t; cvta.to.shared.u64 t, %1; cvt.u32.u64 %0, t; }"
        : "=r"(a) : "l"(p));
    return a;
}
__device__ __forceinline__ void cp16(uint32_t dst, const void* src) {
    asm volatile("cp.async.cg.shared.global [%0], [%1], 16;"
                 :: "r"(dst), "l"(src));
}
#define CP_COMMIT() asm volatile("cp.async.commit_group;" ::: "memory")

__device__ __forceinline__ void ldsm4(uint32_t* r, uint32_t addr) {
    asm volatile("ldmatrix.sync.aligned.m8n8.x4.shared.b16 {%0,%1,%2,%3}, [%4];"
                 : "=r"(r[0]), "=r"(r[1]), "=r"(r[2]), "=r"(r[3]) : "r"(addr));
}
__device__ __forceinline__ void mma16816(float* d, const uint32_t* a,
                                         const uint32_t* b) {
    asm volatile(
        "mma.sync.aligned.m16n8k16.row.col.f32.f16.f16.f32 "
        "{%0,%1,%2,%3}, {%4,%5,%6,%7}, {%8,%9}, {%0,%1,%2,%3};"
        : "+f"(d[0]), "+f"(d[1]), "+f"(d[2]), "+f"(d[3])
        : "r"(a[0]), "r"(a[1]), "r"(a[2]), "r"(a[3]), "r"(b[0]), "r"(b[1]));
}

// ---- fused pre kernel: zero stats | prep W | gather+FM ---------------------
__global__ void pre_k(const int* __restrict__ xc,
                      const float* __restrict__ lin_tab,
                      const float* __restrict__ lat_tab,
                      const float* __restrict__ bias,
                      const float* __restrict__ W1,
                      const float* __restrict__ W2) {
    const int blk = blockIdx.x;
    const int tid = threadIdx.x;

    if (blk < 2048) {                       // ---- gather + FM ----
        int row  = blk * 8 + (tid >> 5);
        int lane = tid & 31;
        int   idx  = 0;
        float linv = 0.f;
        if (lane < NF) {
            idx  = xc[row * NF + lane];
            linv = lin_tab[lane * VOCAB + idx];
        }
        float sdim = 0.f, sq = 0.f;
        unsigned short* xh = &g_Xh[(size_t)row * DIN];
#pragma unroll
        for (int f = 0; f < NF; ++f) {
            int id = __shfl_sync(0xffffffffu, idx, f);
            float e = lat_tab[((size_t)f * VOCAB + id) * ED + lane];
            xh[f * ED + lane] = __half_as_ushort(__float2half(e));
            sdim += e; sq += e * e;
        }
        float t = sdim * sdim - sq;
#pragma unroll
        for (int o = 16; o; o >>= 1) {
            t    += __shfl_xor_sync(0xffffffffu, t, o);
            linv += __shfl_xor_sync(0xffffffffu, linv, o);
        }
        if (lane == 0) g_fm[row] = linv + 0.5f * t + bias[0];
    } else if (blk < 2528) {                // ---- weight prep ----
        const int t1 = DIN * H1N;
        const int tot = t1 + H1N * H2N;
        for (int i = (blk - 2048) * 256 + tid; i < tot; i += 480 * 256) {
            if (i < t1) {
                int k = i / H1N, n = i % H1N;
                g_W1T[n * DIN + k] = __half_as_ushort(__float2half(W1[i]));
            } else {
                int j = i - t1;
                int k = j / H2N, n = j % H2N;
                g_W2T[n * H1N + k] = __half_as_ushort(__float2half(W2[j]));
            }
        }
    } else {                                // ---- zero stats ----
        g_stats1[tid] = 0.f; g_stats1[H1N + tid] = 0.f;
        if (tid < H2N) { g_stats2[tid] = 0.f; g_stats2[H2N + tid] = 0.f; }
    }
}

// ---- GEMM1: single fp16, 2-stage double buffer, fused stats (unchanged) ----
template<int KTOT, int NCOLS>
__global__ __launch_bounds__(256, 2)
void gemm_fp16(const unsigned short* __restrict__ A,
               const unsigned short* __restrict__ Bt,
               const float* __restrict__ bias, float* __restrict__ C,
               float* __restrict__ stats) {
    extern __shared__ char smem[];
    constexpr int STR    = 72;
    constexpr int TILE   = 128 * STR * 2;
    constexpr int STAGE  = 2 * TILE;
    constexpr int NCHUNK = KTOT / 64;
    __shared__ float csum[128], csq[128];

    const uint32_t sb = smem_u32(smem);
    const int tid = threadIdx.x;
    const int lane = tid & 31;
    const int wid = tid >> 5;
    const int warp_m = wid & 3;
    const int warp_n = wid >> 2;
    const int rowBase = blockIdx.x * 128;
    const int colBase = blockIdx.y * 128;

    float acc[2][8][4];
#pragma unroll
    for (int i = 0; i < 2; ++i)
#pragma unroll
        for (int j = 0; j < 8; ++j)
#pragma unroll
            for (int k = 0; k < 4; ++k) acc[i][j][k] = 0.f;

    const int a_row = warp_m * 32 + (lane & 15);
    const int a_col8 = (lane >> 4) << 3;
    const int b_row_base = warp_n * 64 + (lane & 7) + ((lane >> 4) << 3);
    const int b_col8 = ((lane >> 3) & 1) << 3;

    auto load_stage = [&](int kc) {
        const uint32_t base = sb + (kc & 1) * STAGE;
#pragma unroll
        for (int i = tid; i < 128 * 8; i += 256) {
            int row = i >> 3, seg = i & 7;
            uint32_t soff = (uint32_t)(row * STR + seg * 8) * 2;
            size_t ga = (size_t)(rowBase + row) * KTOT + kc * 64 + seg * 8;
            size_t gb = (size_t)(colBase + row) * KTOT + kc * 64 + seg * 8;
            cp16(base + soff,        A + ga);
            cp16(base + TILE + soff, Bt + gb);
        }
        CP_COMMIT();
    };

    load_stage(0);

    for (int kc = 0; kc < NCHUNK; ++kc) {
        if (kc + 1 < NCHUNK) {
            load_stage(kc + 1);
            asm volatile("cp.async.wait_group 1;" ::: "memory");
        } else {
            asm volatile("cp.async.wait_group 0;" ::: "memory");
        }
        __syncthreads();

        const uint32_t base = sb + (kc & 1) * STAGE;
#pragma unroll
        for (int ks = 0; ks < 4; ++ks) {
            uint32_t ah[2][4];
#pragma unroll
            for (int mt = 0; mt < 2; ++mt) {
                uint32_t off = (uint32_t)((a_row + mt * 16) * STR +
                                          ks * 16 + a_col8) * 2;
                ldsm4(ah[mt], base + off);
            }
#pragma unroll
            for (int nb = 0; nb < 4; ++nb) {
                uint32_t bh[4];
                uint32_t off = (uint32_t)((b_row_base + nb * 16) * STR +
                                          ks * 16 + b_col8) * 2;
                ldsm4(bh, base + TILE + off);
#pragma unroll
                for (int mt = 0; mt < 2; ++mt) {
                    mma16816(acc[mt][2 * nb],     ah[mt], bh);
                    mma16816(acc[mt][2 * nb + 1], ah[mt], bh + 2);
                }
            }
        }
        __syncthreads();
    }

    if (tid < 128) { csum[tid] = 0.f; csq[tid] = 0.f; }
    __syncthreads();
#pragma unroll
    for (int nt = 0; nt < 8; ++nt) {
        int cl = warp_n * 64 + nt * 8 + 2 * (lane & 3);
        int c  = colBase + cl;
        float2 bv = *(const float2*)&bias[c];
        float s0 = 0.f, s1 = 0.f, q0 = 0.f, q1 = 0.f;
#pragma unroll
        for (int mt = 0; mt < 2; ++mt) {
            int r0 = rowBase + warp_m * 32 + mt * 16 + (lane >> 2);
            float2 v0 = {acc[mt][nt][0] + bv.x, acc[mt][nt][1] + bv.y};
            float2 v1 = {acc[mt][nt][2] + bv.x, acc[mt][nt][3] + bv.y};
            *(float2*)&C[(size_t)r0 * NCOLS + c]       = v0;
            *(float2*)&C[(size_t)(r0 + 8) * NCOLS + c] = v1;
            s0 += v0.x + v1.x;  s1 += v0.y + v1.y;
            q0 += v0.x * v0.x + v1.x * v1.x;
            q1 += v0.y * v0.y + v1.y * v1.y;
        }
        atomicAdd(&csum[cl], s0);     atomicAdd(&csum[cl + 1], s1);
        atomicAdd(&csq[cl],  q0);     atomicAdd(&csq[cl + 1],  q1);
    }
    __syncthreads();
    if (tid < 128) {
        atomicAdd(&stats[colBase + tid],         csum[tid]);
        atomicAdd(&stats[NCOLS + colBase + tid], csq[tid]);
    }
}

// ---- GEMM2: single fp16, TM=64, 2-stage double buffer, act fused, stats ----
// H2[B x 128] = relu(BN(H1))[B x 256] @ W2t[128 x 256]^T + b2
// Stage s: [A 64x72 fp16][B 128x72 fp16]. Leading load into stage (kc+1)&1,
// wait, sync, compute, trailing sync (gemm1-proven ordering, race-free).
__global__ __launch_bounds__(256, 2)
void gemm2_k(const float* __restrict__ H1,
             const unsigned short* __restrict__ Bt,
             const float* __restrict__ g1, const float* __restrict__ be1,
             const float* __restrict__ bias, float* __restrict__ C,
             float* __restrict__ stats) {
    extern __shared__ char smem[];
    constexpr int KTOT = H1N, NCOLS = H2N;
    constexpr int STR    = 72;
    constexpr int TILE_A = 64 * STR * 2;         // 9216 B
    constexpr int TILE_B = 128 * STR * 2;        // 18432 B
    constexpr int STAGE  = TILE_A + TILE_B;      // 27648 B
    constexpr int NCHUNK = KTOT / 64;            // 4
    __shared__ float sc[H1N], sh[H1N];
    __shared__ float csum[128], csq[128];

    const uint32_t sb = smem_u32(smem);
    const int tid = threadIdx.x;
    const int lane = tid & 31;
    const int wid = tid >> 5;
    const int warp_m = wid & 3;
    const int warp_n = wid >> 2;
    const int rowBase = blockIdx.x * 64;

    {   // BN scale/shift from global stats1
        float s  = g_stats1[tid];
        float sq = g_stats1[H1N + tid];
        float mean = s * (1.f / BATCH);
        float var  = sq * (1.f / BATCH) - mean * mean;
        float rstd = rsqrtf(var + BN_EPS);
        float scl  = g1[tid] * rstd;
        sc[tid] = scl;
        sh[tid] = be1[tid] - mean * scl;
    }
    __syncthreads();

    float acc[8][4];
#pragma unroll
    for (int j = 0; j < 8; ++j)
#pragma unroll
        for (int k = 0; k < 4; ++k) acc[j][k] = 0.f;

    const int a_row = warp_m * 16 + (lane & 15);
    const int a_col8 = (lane >> 4) << 3;
    const int b_row_base = warp_n * 64 + (lane & 7) + ((lane >> 4) << 3);
    const int b_col8 = ((lane >> 3) & 1) << 3;

    const int al_row = tid >> 2;          // 0..63
    const int al_seg = tid & 3;           // 0..3

    // A path: ldg fp32 H1 chunk into regs
    float4 ra[4];
    auto ldg_A = [&](int kc) {
#pragma unroll
        for (int p = 0; p < 4; ++p) {
            int kk = kc * 64 + (al_seg + p * 4) * 4;
            ra[p] = *(const float4*)&H1[(size_t)(rowBase + al_row) * KTOT + kk];
        }
    };
    // BN + ReLU + fp16 convert -> stage smem (race-free: target stage's
    // readers retired at the previous trailing __syncthreads)
    auto store_A = [&](int kc) {
        const uint32_t base = (kc & 1) * STAGE;
#pragma unroll
        for (int p = 0; p < 4; ++p) {
            int kk = kc * 64 + (al_seg + p * 4) * 4;
            int cl = kk & (H1N - 1);
            float h0 = fmaxf(fmaf(ra[p].x, sc[cl + 0], sh[cl + 0]), 0.f);
            float h1 = fmaxf(fmaf(ra[p].y, sc[cl + 1], sh[cl + 1]), 0.f);
            float h2 = fmaxf(fmaf(ra[p].z, sc[cl + 2], sh[cl + 2]), 0.f);
            float h3 = fmaxf(fmaf(ra[p].w, sc[cl + 3], sh[cl + 3]), 0.f);
            __half2 a = __floats2half2_rn(h0, h1);
            __half2 b = __floats2half2_rn(h2, h3);
            uint32_t soff = base +
                (uint32_t)(al_row * STR + (al_seg + p * 4) * 4) * 2;
            *(uint32_t*)(smem + soff)     = *(uint32_t*)&a;
            *(uint32_t*)(smem + soff + 4) = *(uint32_t*)&b;
        }
    };
    auto load_B = [&](int kc) {
        const uint32_t base = sb + (kc & 1) * STAGE + TILE_A;
#pragma unroll
        for (int i = tid; i < 128 * 8; i += 256) {
            int row = i >> 3, seg = i & 7;
            uint32_t soff = (uint32_t)(row * STR + seg * 8) * 2;
            size_t gb = (size_t)row * KTOT + kc * 64 + seg * 8;
            cp16(base + soff, Bt + gb);
        }
        CP_COMMIT();
    };

    // prologue: stage0 fully loaded; A1 regs in flight
    ldg_A(0);
    load_B(0);
    store_A(0);
    ldg_A(1);

    for (int kc = 0; kc < NCHUNK; ++kc) {
        if (kc + 1 < NCHUNK) {
            load_B(kc + 1);
            store_A(kc + 1);                 // regs from previous iteration
            if (kc + 2 < NCHUNK) ldg_A(kc + 2);
            asm volatile("cp.async.wait_group 1;" ::: "memory");
        } else {
            asm volatile("cp.async.wait_group 0;" ::: "memory");
        }
        __syncthreads();

        const uint32_t baseA = sb + (kc & 1) * STAGE;
        const uint32_t baseB = baseA + TILE_A;
#pragma unroll
        for (int ks = 0; ks < 4; ++ks) {
            uint32_t ah[4];
            ldsm4(ah, baseA + (uint32_t)(a_row * STR + ks * 16 + a_col8) * 2);
#pragma unroll
            for (int nb = 0; nb < 4; ++nb) {
                uint32_t bh[4];
                uint32_t off = (uint32_t)((b_row_base + nb * 16) * STR +
                                          ks * 16 + b_col8) * 2;
                ldsm4(bh, baseB + off);
                mma16816(acc[2 * nb],     ah, bh);
                mma16816(acc[2 * nb + 1], ah, bh + 2);
            }
        }
        __syncthreads();
    }

    // epilogue: bias add, store, fused column stats
    if (tid < 128) { csum[tid] = 0.f; csq[tid] = 0.f; }
    __syncthreads();
#pragma unroll
    for (int nt = 0; nt < 8; ++nt) {
        int cl = warp_n * 64 + nt * 8 + 2 * (lane & 3);
        float2 bv = *(const float2*)&bias[cl];
        int r0 = rowBase + warp_m * 16 + (lane >> 2);
        float2 v0 = {acc[nt][0] + bv.x, acc[nt][1] + bv.y};
        float2 v1 = {acc[nt][2] + bv.x, acc[nt][3] + bv.y};
        *(float2*)&C[(size_t)r0 * NCOLS + cl]       = v0;
        *(float2*)&C[(size_t)(r0 + 8) * NCOLS + cl] = v1;
        atomicAdd(&csum[cl],     v0.x + v1.x);
        atomicAdd(&csum[cl + 1], v0.y + v1.y);
        atomicAdd(&csq[cl],      v0.x * v0.x + v1.x * v1.x);
        atomicAdd(&csq[cl + 1],  v0.y * v0.y + v1.y * v1.y);
    }
    __syncthreads();
    if (tid < 128) {
        atomicAdd(&stats[tid],         csum[tid]);
        atomicAdd(&stats[NCOLS + tid], csq[tid]);
    }
}

// ---- final: out = fm + relu(BN(H2)) @ W3 + b3 ------------------------------
__global__ void final_k(const float* __restrict__ W3, const float* __restrict__ b3,
                        const float* __restrict__ g2, const float* __restrict__ be2,
                        float* __restrict__ out) {
    __shared__ float sc[H2N], sh[H2N], w3s[H2N];
    int tid = threadIdx.x;
    if (tid < H2N) {
        float s  = g_stats2[tid];
        float sq = g_stats2[H2N + tid];
        float mean = s * (1.f / BATCH);
        float var  = sq * (1.f / BATCH) - mean * mean;
        float rstd = rsqrtf(var + BN_EPS);
        float scl  = g2[tid] * rstd;
        sc[tid] = scl;
        sh[tid] = be2[tid] - mean * scl;
        w3s[tid] = W3[tid];
    }
    __syncthreads();
    int warp = tid >> 5, lane = tid & 31;
    int row = blockIdx.x * 8 + warp;
    float acc = 0.f;
#pragma unroll
    for (int j = 0; j < 4; ++j) {
        int c = lane + j * 32;
        float v = g_H2[(size_t)row * H2N + c];
        acc += fmaxf(fmaf(v, sc[c], sh[c]), 0.f) * w3s[c];
    }
#pragma unroll
    for (int o = 16; o; o >>= 1) acc += __shfl_xor_sync(0xffffffffu, acc, o);
    if (lane == 0) out[row] = g_fm[row] + acc + b3[0];
}

// ---------------------------------------------------------------------------
extern "C" void kernel_launch(void* const* d_in, const int* in_sizes, int n_in,
                              void* d_out, int out_size) {
    const int*   xc   = (const int*)  d_in[0];
    const float* lin  = (const float*)d_in[1];
    const float* lat  = (const float*)d_in[2];
    const float* W1   = (const float*)d_in[3];
    const float* b1   = (const float*)d_in[4];
    const float* g1   = (const float*)d_in[5];
    const float* be1  = (const float*)d_in[6];
    const float* W2   = (const float*)d_in[7];
    const float* b2   = (const float*)d_in[8];
    const float* g2   = (const float*)d_in[9];
    const float* be2  = (const float*)d_in[10];
    const float* W3   = (const float*)d_in[11];
    const float* b3   = (const float*)d_in[12];
    const float* bias = (const float*)d_in[13];
    float* out = (float*)d_out;

    unsigned short *pXh, *pW1, *pW2;
    float *pH1, *pH2, *pS1, *pS2;
    cudaGetSymbolAddress((void**)&pXh, g_Xh);
    cudaGetSymbolAddress((void**)&pW1, g_W1T);
    cudaGetSymbolAddress((void**)&pW2, g_W2T);
    cudaGetSymbolAddress((void**)&pH1, g_H1);
    cudaGetSymbolAddress((void**)&pH2, g_H2);
    cudaGetSymbolAddress((void**)&pS1, g_stats1);
    cudaGetSymbolAddress((void**)&pS2, g_stats2);

    constexpr int SMEM1 = 2 * 2 * 128 * 72 * 2;            // 73728
    constexpr int SMEM2 = 2 * (64 + 128) * 72 * 2;         // 55296
    cudaFuncSetAttribute(gemm_fp16<DIN, H1N>,
                         cudaFuncAttributeMaxDynamicSharedMemorySize, SMEM1);
    cudaFuncSetAttribute(gemm2_k,
                         cudaFuncAttributeMaxDynamicSharedMemorySize, SMEM2);

    pre_k<<<2529, 256>>>(xc, lin, lat, bias, W1, W2);
    gemm_fp16<DIN, H1N><<<dim3(BATCH / 128, H1N / 128), 256, SMEM1>>>(
        pXh, pW1, b1, pH1, pS1);
    gemm2_k<<<BATCH / 64, 256, SMEM2>>>(pH1, pW2, g1, be1, b2, pH2, pS2);
    final_k<<<BATCH / 8, 256>>>(W3, b3, g2, be2, out);
}